// round 3
// baseline (speedup 1.0000x reference)
#include <cuda_runtime.h>

#define EDIM 1024
#define LSEQ 2048
#define NB   4
#define NH   16
#define MTOK (NB * LSEQ)
#define QKVC 3072

__device__ float g_Wc[3u * 1024u * 1024u];
__device__ float g_qkv[(size_t)MTOK * QKVC];
__device__ float g_att[(size_t)MTOK * EDIM];

// fp32 SGEMM: C(M,N) = A(M,K) * op(B). BT: B is (N,K) row-major -> C=A*B^T.
// 128x128x8 tiles, 256 threads, 8x8 microtile, register prefetch.
template <bool BT>
__device__ __forceinline__ void sgemm_body(const float* __restrict__ A,
                                           const float* __restrict__ B,
                                           float* __restrict__ C,
                                           int M, int Nn, int K)
{
    __shared__ float As[8][128];
    __shared__ float Bs[8][128];
    const int tid = threadIdx.x;
    const int tx = tid & 15, ty = tid >> 4;
    const int m0 = blockIdx.y * 128, n0 = blockIdx.x * 128;

    const int a_row = tid >> 1, a_k = (tid & 1) * 4;
    const float* Ap = A + (size_t)(m0 + a_row) * K + a_k;

    const float* Bp;
    int b_row = 0, b_k = 0, b_n = 0;
    if (BT) { b_row = tid >> 1; b_k = (tid & 1) * 4;
              Bp = B + (size_t)(n0 + b_row) * K + b_k; }
    else    { b_k = tid >> 5; b_n = (tid & 31) * 4;
              Bp = B + (size_t)b_k * Nn + n0 + b_n; }

    float acc[8][8];
#pragma unroll
    for (int i = 0; i < 8; ++i)
#pragma unroll
        for (int j = 0; j < 8; ++j) acc[i][j] = 0.f;

    float4 av = *(const float4*)Ap;
    float4 bv = *(const float4*)Bp;

    const int ktiles = K >> 3;
    for (int kt = 0; kt < ktiles; ++kt) {
        __syncthreads();
        As[a_k + 0][a_row] = av.x; As[a_k + 1][a_row] = av.y;
        As[a_k + 2][a_row] = av.z; As[a_k + 3][a_row] = av.w;
        if (BT) {
            Bs[b_k + 0][b_row] = bv.x; Bs[b_k + 1][b_row] = bv.y;
            Bs[b_k + 2][b_row] = bv.z; Bs[b_k + 3][b_row] = bv.w;
        } else {
            *(float4*)&Bs[b_k][b_n] = bv;
        }
        __syncthreads();
        if (kt + 1 < ktiles) {
            av = *(const float4*)(Ap + (size_t)(kt + 1) * 8);
            if (BT) bv = *(const float4*)(Bp + (size_t)(kt + 1) * 8);
            else    bv = *(const float4*)(Bp + (size_t)(kt + 1) * 8 * Nn);
        }
#pragma unroll
        for (int k = 0; k < 8; ++k) {
            float ar[8], br[8];
            *(float4*)&ar[0] = *(const float4*)&As[k][4 * ty];
            *(float4*)&ar[4] = *(const float4*)&As[k][64 + 4 * ty];
            *(float4*)&br[0] = *(const float4*)&Bs[k][4 * tx];
            *(float4*)&br[4] = *(const float4*)&Bs[k][64 + 4 * tx];
#pragma unroll
            for (int i = 0; i < 8; ++i)
#pragma unroll
                for (int j = 0; j < 8; ++j) acc[i][j] += ar[i] * br[j];
        }
    }
#pragma unroll
    for (int i = 0; i < 8; ++i) {
        const int m = m0 + (i >> 2) * 64 + 4 * ty + (i & 3);
        *(float4*)&C[(size_t)m * Nn + n0 + 4 * tx] =
            make_float4(acc[i][0], acc[i][1], acc[i][2], acc[i][3]);
        *(float4*)&C[(size_t)m * Nn + n0 + 64 + 4 * tx] =
            make_float4(acc[i][4], acc[i][5], acc[i][6], acc[i][7]);
    }
}

__global__ void __launch_bounds__(256) k_combine(
    const float* __restrict__ Wq, const float* __restrict__ Wk,
    const float* __restrict__ Wv, const float* __restrict__ Wqp,
    const float* __restrict__ Wkp, const float* __restrict__ Wvp)
{
    const int z = blockIdx.z;
    const float* Am = (z == 0) ? Wqp : (z == 1) ? Wkp : Wvp;
    const float* Bm = (z == 0) ? Wq  : (z == 1) ? Wk  : Wv;
    sgemm_body<false>(Am, Bm, g_Wc + (size_t)z * 1024 * 1024, 1024, 1024, 1024);
}

__global__ void __launch_bounds__(256) k_qkv(const float* __restrict__ x)
{
    sgemm_body<true>(x, g_Wc, g_qkv, MTOK, QKVC, EDIM);
}

__global__ void __launch_bounds__(256) k_out(const float* __restrict__ Wout,
                                             float* __restrict__ outp)
{
    sgemm_body<true>(g_att, Wout, outp, MTOK, EDIM, EDIM);
}

// Flash attention fp32. CTA = 64 Q rows of one (n,h); 64x64 KV tiles.
// 16x16 threads, 4x4 microtile. K^T swizzled in smem; P aliases K^T.
__global__ void __launch_bounds__(256) k_att()
{
    __shared__ float Qs[64 * 64];
    __shared__ float KT[64 * 64];
    __shared__ float Vs[64 * 64];
    float* Ps = KT;

    const int tid = threadIdx.x;
    const int tx = tid & 15, ty = tid >> 4;
    const int n = blockIdx.y >> 4, h = blockIdx.y & 15;
    const int l0 = blockIdx.x * 64;

    const float* qb = g_qkv + ((size_t)n * LSEQ + l0) * QKVC + h * 64;
    const float* kb = g_qkv + (size_t)n * LSEQ * QKVC + 1024 + h * 64;
    const float* vb = kb + 1024;

    {   // Q tile, pre-scaled by 1/sqrt(64)
        const int c = tx * 4;
#pragma unroll
        for (int m = ty; m < 64; m += 16) {
            float4 v = *(const float4*)(qb + (size_t)m * QKVC + c);
            v.x *= 0.125f; v.y *= 0.125f; v.z *= 0.125f; v.w *= 0.125f;
            *(float4*)&Qs[m * 64 + c] = v;
        }
    }

    float4 o[4];
    float mrow[4], lrow[4];
#pragma unroll
    for (int i = 0; i < 4; ++i) {
        o[i] = make_float4(0.f, 0.f, 0.f, 0.f);
        mrow[i] = -3.0e38f; lrow[i] = 0.f;
    }

    for (int it = 0; it < LSEQ / 64; ++it) {
        const int lk = it * 64;
        __syncthreads();           // prev pass2 done; covers Q store on it==0
        {   // K transposed (XOR-swizzled at float4 granularity) + V row-major
            const int kk4 = tx;
#pragma unroll
            for (int j = ty; j < 64; j += 16) {
                float4 kv = *(const float4*)(kb + (size_t)(lk + j) * QKVC + kk4 * 4);
                const int colb = 4 * ((j >> 2) ^ kk4) + (j & 3);
                KT[(4 * kk4 + 0) * 64 + colb] = kv.x;
                KT[(4 * kk4 + 1) * 64 + colb] = kv.y;
                KT[(4 * kk4 + 2) * 64 + colb] = kv.z;
                KT[(4 * kk4 + 3) * 64 + colb] = kv.w;
                *(float4*)&Vs[j * 64 + kk4 * 4] =
                    *(const float4*)(vb + (size_t)(lk + j) * QKVC + kk4 * 4);
            }
        }
        __syncthreads();

        // Pass 1: S = Q * K^T (rows 4ty+i, cols 4tx+c)
        float4 s[4];
#pragma unroll
        for (int i = 0; i < 4; ++i) s[i] = make_float4(0.f, 0.f, 0.f, 0.f);
#pragma unroll
        for (int k4 = 0; k4 < 16; ++k4) {
            const int kk = k4 * 4;
            const int pc = 4 * (tx ^ k4);
            float4 t0 = *(const float4*)&KT[(kk + 0) * 64 + pc];
            float4 t1 = *(const float4*)&KT[(kk + 1) * 64 + pc];
            float4 t2 = *(const float4*)&KT[(kk + 2) * 64 + pc];
            float4 t3 = *(const float4*)&KT[(kk + 3) * 64 + pc];
#pragma unroll
            for (int i = 0; i < 4; ++i) {
                float4 q = *(const float4*)&Qs[(4 * ty + i) * 64 + kk];
                s[i].x += q.x * t0.x + q.y * t1.x + q.z * t2.x + q.w * t3.x;
                s[i].y += q.x * t0.y + q.y * t1.y + q.z * t2.y + q.w * t3.y;
                s[i].z += q.x * t0.z + q.y * t1.z + q.z * t2.z + q.w * t3.z;
                s[i].w += q.x * t0.w + q.y * t1.w + q.z * t2.w + q.w * t3.w;
            }
        }
        __syncthreads();  // KT reads done -> safe to alias as Ps

        // Online softmax: stats in registers, reduce over the 16 tx lanes
#pragma unroll
        for (int i = 0; i < 4; ++i) {
            float rm = fmaxf(fmaxf(s[i].x, s[i].y), fmaxf(s[i].z, s[i].w));
#pragma unroll
            for (int off = 8; off >= 1; off >>= 1)
                rm = fmaxf(rm, __shfl_xor_sync(0xffffffffu, rm, off));
            const float mn = fmaxf(mrow[i], rm);
            const float al = __expf(mrow[i] - mn);
            mrow[i] = mn;
            s[i].x = __expf(s[i].x - mn); s[i].y = __expf(s[i].y - mn);
            s[i].z = __expf(s[i].z - mn); s[i].w = __expf(s[i].w - mn);
            float rs = s[i].x + s[i].y + s[i].z + s[i].w;
#pragma unroll
            for (int off = 8; off >= 1; off >>= 1)
                rs += __shfl_xor_sync(0xffffffffu, rs, off);
            lrow[i] = lrow[i] * al + rs;
            o[i].x *= al; o[i].y *= al; o[i].z *= al; o[i].w *= al;
            *(float4*)&Ps[(4 * ty + i) * 64 + 4 * tx] = s[i];
        }
        __syncthreads();

        // Pass 2: O += P * V (rows 4ty+i, value-dims 4tx+c)
#pragma unroll
        for (int j4 = 0; j4 < 16; ++j4) {
            const int j = j4 * 4;
            float4 v0 = *(const float4*)&Vs[(j + 0) * 64 + 4 * tx];
            float4 v1 = *(const float4*)&Vs[(j + 1) * 64 + 4 * tx];
            float4 v2 = *(const float4*)&Vs[(j + 2) * 64 + 4 * tx];
            float4 v3 = *(const float4*)&Vs[(j + 3) * 64 + 4 * tx];
#pragma unroll
            for (int i = 0; i < 4; ++i) {
                float4 p = *(const float4*)&Ps[(4 * ty + i) * 64 + j];
                o[i].x += p.x * v0.x + p.y * v1.x + p.z * v2.x + p.w * v3.x;
                o[i].y += p.x * v0.y + p.y * v1.y + p.z * v2.y + p.w * v3.y;
                o[i].z += p.x * v0.z + p.y * v1.z + p.z * v2.z + p.w * v3.z;
                o[i].w += p.x * v0.w + p.y * v1.w + p.z * v2.w + p.w * v3.w;
            }
        }
    }

#pragma unroll
    for (int i = 0; i < 4; ++i) {
        const float inv = 1.0f / lrow[i];
        float4 r = make_float4(o[i].x * inv, o[i].y * inv, o[i].z * inv, o[i].w * inv);
        g_att[((size_t)n * LSEQ + l0 + 4 * ty + i) * EDIM + h * 64 + 4 * tx] =
            r.x;
        *(float4*)&g_att[((size_t)n * LSEQ + l0 + 4 * ty + i) * EDIM + h * 64 + 4 * tx] = r;
    }
}

extern "C" void kernel_launch(void* const* d_in, const int* in_sizes, int n_in,
                              void* d_out, int out_size)
{
    const float* x    = (const float*)d_in[0];
    const float* Wq   = (const float*)d_in[1];
    const float* Wk   = (const float*)d_in[2];
    const float* Wv   = (const float*)d_in[3];
    const float* Wqp  = (const float*)d_in[4];
    const float* Wkp  = (const float*)d_in[5];
    const float* Wvp  = (const float*)d_in[6];
    const float* Wout = (const float*)d_in[7];
    float* outp = (float*)d_out;

    k_combine<<<dim3(8, 8, 3), 256>>>(Wq, Wk, Wv, Wqp, Wkp, Wvp);
    k_qkv<<<dim3(QKVC / 128, MTOK / 128), 256>>>(x);
    k_att<<<dim3(LSEQ / 64, NB * NH), 256>>>();
    k_out<<<dim3(EDIM / 128, MTOK / 128), 256>>>(Wout, outp);
}

// round 7
// speedup vs baseline: 1.0531x; 1.0531x over previous
#include <cuda_runtime.h>
#include <cuda_bf16.h>
#include <cstdint>

#define EDIM 1024
#define LSEQ 2048
#define NB   4
#define NH   16
#define MTOK 8192
#define QKVC 3072

// bf16 hi/lo planes + fp32 qkv scratch (allocation-free rule: __device__ globals)
__device__ __nv_bfloat16 g_xh[(size_t)MTOK * EDIM], g_xl[(size_t)MTOK * EDIM];
__device__ __nv_bfloat16 g_wh[7u * 1048576u],       g_wl[7u * 1048576u];
__device__ __nv_bfloat16 g_tmph[(size_t)MTOK * QKVC], g_tmpl[(size_t)MTOK * QKVC];
__device__ float         g_qkv[(size_t)MTOK * QKVC];
__device__ __nv_bfloat16 g_atth[(size_t)MTOK * EDIM], g_attl[(size_t)MTOK * EDIM];

// ---- helpers --------------------------------------------------------------
__device__ __forceinline__ uint32_t smem_u32(const void* p) {
    uint32_t a;
    asm("{ .reg .u64 t; cvta.to.shared.u64 t, %1; cvt.u32.u64 %0, t; }"
        : "=r"(a) : "l"(p));
    return a;
}
// split (a,b) fp32 -> packed bf16 hi pair + bf16 lo (residual) pair
__device__ __forceinline__ void split2(float a, float b, uint32_t& hi, uint32_t& lo) {
    uint32_t ab = __float_as_uint(a), bb = __float_as_uint(b);
    hi = __byte_perm(ab, bb, 0x7632);                 // low16 = a_hi, high16 = b_hi
    float ar = a - __uint_as_float(ab & 0xFFFF0000u); // exact residuals
    float br = b - __uint_as_float(bb & 0xFFFF0000u);
    asm("cvt.rn.bf16x2.f32 %0, %1, %2;" : "=r"(lo) : "f"(br), "f"(ar));
}
__device__ __forceinline__ void ldsm4(uint32_t* r, uint32_t a) {
    asm volatile("ldmatrix.sync.aligned.m8n8.x4.shared.b16 {%0,%1,%2,%3}, [%4];"
                 : "=r"(r[0]), "=r"(r[1]), "=r"(r[2]), "=r"(r[3]) : "r"(a));
}
__device__ __forceinline__ void mma_bf16(float* c, const uint32_t* a,
                                         uint32_t b0, uint32_t b1) {
    asm volatile("mma.sync.aligned.m16n8k16.row.col.f32.bf16.bf16.f32 "
                 "{%0,%1,%2,%3}, {%4,%5,%6,%7}, {%8,%9}, {%0,%1,%2,%3};"
                 : "+f"(c[0]), "+f"(c[1]), "+f"(c[2]), "+f"(c[3])
                 : "r"(a[0]), "r"(a[1]), "r"(a[2]), "r"(a[3]), "r"(b0), "r"(b1));
}
__device__ __forceinline__ void cpa16(uint32_t d, const void* s) {
    asm volatile("cp.async.cg.shared.global [%0], [%1], 16;" :: "r"(d), "l"(s)
                 : "memory");
}

// ---- input converter: fp32 -> hi/lo bf16 planes ---------------------------
__global__ void __launch_bounds__(256) k_cvt(const float4* __restrict__ in,
                                             uint2* __restrict__ hi,
                                             uint2* __restrict__ lo, int n4)
{
    int i = blockIdx.x * blockDim.x + threadIdx.x;
    if (i >= n4) return;
    float4 v = in[i];
    uint32_t h0, l0, h1, l1;
    split2(v.x, v.y, h0, l0);
    split2(v.z, v.w, h1, l1);
    hi[i] = make_uint2(h0, h1);
    lo[i] = make_uint2(l0, l1);
}

// ---- split-bf16 mma.sync GEMM: C = A * B^T --------------------------------
// Tile 128x128, K-slab 32, 2-stage cp.async. smem rows padded to 80B
// (12-bank stride -> conflict-free ldmatrix). OUT: 0 = fp32 C, 1 = bf16 hi/lo C.
#define RP    80
#define PLANE 10240   /* 128*80 */
#define BUF   40960   /* 4 planes: Ah|Al|Bh|Bl */
#define DSM   81920

template <int OUT>
__global__ void __launch_bounds__(256, 2) k_gemm(
    const __nv_bfloat16* __restrict__ Ah, const __nv_bfloat16* __restrict__ Al,
    int lda, int aoff,
    const __nv_bfloat16* __restrict__ Bh, const __nv_bfloat16* __restrict__ Bl,
    float* __restrict__ Cf, __nv_bfloat16* __restrict__ Ch,
    __nv_bfloat16* __restrict__ Cl, int ldc, int coff)
{
    extern __shared__ __align__(16) char sm[];
    const int tid = threadIdx.x;
    const int lane = tid & 31, wid = tid >> 5;
    const int wm = wid & 1, wn = wid >> 1;        // warp grid 2(m) x 4(n)
    const int z = blockIdx.z;
    const int m0 = blockIdx.y * 128, n0 = blockIdx.x * 128;

    const __nv_bfloat16* Azh = Ah + (size_t)z * aoff;
    const __nv_bfloat16* Azl = Al + (size_t)z * aoff;
    const __nv_bfloat16* Bzh = Bh + (size_t)z * 1048576u;
    const __nv_bfloat16* Bzl = Bl + (size_t)z * 1048576u;

    const int row = tid >> 1, half = tid & 1;     // loader mapping
    const __nv_bfloat16* pAh = Azh + (size_t)(m0 + row) * lda + half * 16;
    const __nv_bfloat16* pAl = Azl + (size_t)(m0 + row) * lda + half * 16;
    const __nv_bfloat16* pBh = Bzh + (size_t)(n0 + row) * 1024 + half * 16;
    const __nv_bfloat16* pBl = Bzl + (size_t)(n0 + row) * 1024 + half * 16;
    const uint32_t sb = smem_u32(sm);
    const uint32_t drow = (uint32_t)row * RP + half * 32;

    auto load_slab = [&](int buf, int kt) {
        const uint32_t d = sb + buf * BUF + drow;
        const int ko = kt * 32;
        cpa16(d,                 pAh + ko); cpa16(d + 16,             pAh + ko + 8);
        cpa16(d + PLANE,         pAl + ko); cpa16(d + PLANE + 16,     pAl + ko + 8);
        cpa16(d + 2 * PLANE,     pBh + ko); cpa16(d + 2 * PLANE + 16, pBh + ko + 8);
        cpa16(d + 3 * PLANE,     pBl + ko); cpa16(d + 3 * PLANE + 16, pBl + ko + 8);
        asm volatile("cp.async.commit_group;" ::: "memory");
    };

    float acc[4][4][4];
#pragma unroll
    for (int i = 0; i < 4; ++i)
#pragma unroll
        for (int j = 0; j < 4; ++j)
#pragma unroll
            for (int r = 0; r < 4; ++r) acc[i][j][r] = 0.f;

    load_slab(0, 0);
    load_slab(1, 1);

    const uint32_t a_base = (uint32_t)(wm * 64 + (lane & 15)) * RP + (lane >> 4) * 16;
    const uint32_t b_base = 2 * PLANE + (uint32_t)(wn * 32 + (lane & 15)) * RP
                            + (lane >> 4) * 16;

    for (int kt = 0; kt < 32; ++kt) {
        if (kt < 30) asm volatile("cp.async.wait_group 1;" ::: "memory");
        else         asm volatile("cp.async.wait_group 0;" ::: "memory");
        __syncthreads();
        const uint32_t bufb = sb + (kt & 1) * BUF;
#pragma unroll
        for (int s = 0; s < 2; ++s) {              // two k16 steps per slab
            const uint32_t stepb = bufb + s * 32;
            uint32_t ah[4][4], bh[2][4], bl[2][4];
#pragma unroll
            for (int mi = 0; mi < 4; ++mi) ldsm4(ah[mi], stepb + a_base + mi * 1280);
#pragma unroll
            for (int p = 0; p < 2; ++p) ldsm4(bh[p], stepb + b_base + p * 1280);
#pragma unroll
            for (int mi = 0; mi < 4; ++mi)
#pragma unroll
                for (int p = 0; p < 2; ++p) {      // Ah * Bh
                    mma_bf16(acc[mi][2 * p],     ah[mi], bh[p][0], bh[p][2]);
                    mma_bf16(acc[mi][2 * p + 1], ah[mi], bh[p][1], bh[p][3]);
                }
#pragma unroll
            for (int p = 0; p < 2; ++p) ldsm4(bl[p], stepb + b_base + PLANE + p * 1280);
#pragma unroll
            for (int mi = 0; mi < 4; ++mi)
#pragma unroll
                for (int p = 0; p < 2; ++p) {      // Ah * Bl
                    mma_bf16(acc[mi][2 * p],     ah[mi], bl[p][0], bl[p][2]);
                    mma_bf16(acc[mi][2 * p + 1], ah[mi], bl[p][1], bl[p][3]);
                }
#pragma unroll
            for (int mi = 0; mi < 4; ++mi) ldsm4(ah[mi], stepb + a_base + PLANE + mi * 1280);
#pragma unroll
            for (int mi = 0; mi < 4; ++mi)
#pragma unroll
                for (int p = 0; p < 2; ++p) {      // Al * Bh
                    mma_bf16(acc[mi][2 * p],     ah[mi], bh[p][0], bh[p][2]);
                    mma_bf16(acc[mi][2 * p + 1], ah[mi], bh[p][1], bh[p][3]);
                }
        }
        __syncthreads();
        if (kt + 2 < 32) load_slab(kt & 1, kt + 2);
    }

    const int t4 = lane >> 2, t2 = lane & 3;
#pragma unroll
    for (int mi = 0; mi < 4; ++mi) {
        const int r0 = m0 + wm * 64 + mi * 16 + t4;
#pragma unroll
        for (int nj = 0; nj < 4; ++nj) {
            const int cc = n0 + wn * 32 + (nj >> 1) * 16 + (nj & 1) * 8 + 2 * t2;
            const float* c = acc[mi][nj];
            const size_t o = (size_t)r0 * ldc + (size_t)z * coff + cc;
            if (OUT == 0) {
                *(float2*)&Cf[o]           = make_float2(c[0], c[1]);
                *(float2*)&Cf[o + 8 * ldc] = make_float2(c[2], c[3]);
            } else {
                uint32_t h, l;
                split2(c[0], c[1], h, l);
                *(uint32_t*)&Ch[o] = h;           *(uint32_t*)&Cl[o] = l;
                split2(c[2], c[3], h, l);
                *(uint32_t*)&Ch[o + 8 * ldc] = h; *(uint32_t*)&Cl[o + 8 * ldc] = l;
            }
        }
    }
}

// ---- flash attention fp32 (R3-proven), epilogue emits bf16 hi/lo ----------
__global__ void __launch_bounds__(256) k_att()
{
    __shared__ float Qs[64 * 64];
    __shared__ float KT[64 * 64];
    __shared__ float Vs[64 * 64];
    float* Ps = KT;

    const int tid = threadIdx.x;
    const int tx = tid & 15, ty = tid >> 4;
    const int n = blockIdx.y >> 4, h = blockIdx.y & 15;
    const int l0 = blockIdx.x * 64;

    const float* qb = g_qkv + ((size_t)n * LSEQ + l0) * QKVC + h * 64;
    const float* kb = g_qkv + (size_t)n * LSEQ * QKVC + 1024 + h * 64;
    const float* vb = kb + 1024;

    {
        const int c = tx * 4;
#pragma unroll
        for (int m = ty; m < 64; m += 16) {
            float4 v = *(const float4*)(qb + (size_t)m * QKVC + c);
            v.x *= 0.125f; v.y *= 0.125f; v.z *= 0.125f; v.w *= 0.125f;
            *(float4*)&Qs[m * 64 + c] = v;
        }
    }

    float4 o[4];
    float mrow[4], lrow[4];
#pragma unroll
    for (int i = 0; i < 4; ++i) {
        o[i] = make_float4(0.f, 0.f, 0.f, 0.f);
        mrow[i] = -3.0e38f; lrow[i] = 0.f;
    }

    for (int it = 0; it < LSEQ / 64; ++it) {
        const int lk = it * 64;
        __syncthreads();
        {
            const int kk4 = tx;
#pragma unroll
            for (int j = ty; j < 64; j += 16) {
                float4 kv = *(const float4*)(kb + (size_t)(lk + j) * QKVC + kk4 * 4);
                const int colb = 4 * ((j >> 2) ^ kk4) + (j & 3);
                KT[(4 * kk4 + 0) * 64 + colb] = kv.x;
                KT[(4 * kk4 + 1) * 64 + colb] = kv.y;
                KT[(4 * kk4 + 2) * 64 + colb] = kv.z;
                KT[(4 * kk4 + 3) * 64 + colb] = kv.w;
                *(float4*)&Vs[j * 64 + kk4 * 4] =
                    *(const float4*)(vb + (size_t)(lk + j) * QKVC + kk4 * 4);
            }
        }
        __syncthreads();

        float4 s[4];
#pragma unroll
        for (int i = 0; i < 4; ++i) s[i] = make_float4(0.f, 0.f, 0.f, 0.f);
#pragma unroll
        for (int k4 = 0; k4 < 16; ++k4) {
            const int kk = k4 * 4;
            const int pc = 4 * (tx ^ k4);
            float4 t0 = *(const float4*)&KT[(kk + 0) * 64 + pc];
            float4 t1 = *(const float4*)&KT[(kk + 1) * 64 + pc];
            float4 t2 = *(const float4*)&KT[(kk + 2) * 64 + pc];
            float4 t3 = *(const float4*)&KT[(kk + 3) * 64 + pc];
#pragma unroll
            for (int i = 0; i < 4; ++i) {
                float4 q = *(const float4*)&Qs[(4 * ty + i) * 64 + kk];
                s[i].x += q.x * t0.x + q.y * t1.x + q.z * t2.x + q.w * t3.x;
                s[i].y += q.x * t0.y + q.y * t1.y + q.z * t2.y + q.w * t3.y;
                s[i].z += q.x * t0.z + q.y * t1.z + q.z * t2.z + q.w * t3.z;
                s[i].w += q.x * t0.w + q.y * t1.w + q.z * t2.w + q.w * t3.w;
            }
        }
        __syncthreads();

#pragma unroll
        for (int i = 0; i < 4; ++i) {
            float rm = fmaxf(fmaxf(s[i].x, s[i].y), fmaxf(s[i].z, s[i].w));
#pragma unroll
            for (int off = 8; off >= 1; off >>= 1)
                rm = fmaxf(rm, __shfl_xor_sync(0xffffffffu, rm, off));
            const float mn = fmaxf(mrow[i], rm);
            const float al = __expf(mrow[i] - mn);
            mrow[i] = mn;
            s[i].x = __expf(s[i].x - mn); s[i].y = __expf(s[i].y - mn);
            s[i].z = __expf(s[i].z - mn); s[i].w = __expf(s[i].w - mn);
            float rs = s[i].x + s[i].y + s[i].z + s[i].w;
#pragma unroll
            for (int off = 8; off >= 1; off >>= 1)
                rs += __shfl_xor_sync(0xffffffffu, rs, off);
            lrow[i] = lrow[i] * al + rs;
            o[i].x *= al; o[i].y *= al; o[i].z *= al; o[i].w *= al;
            *(float4*)&Ps[(4 * ty + i) * 64 + 4 * tx] = s[i];
        }
        __syncthreads();

#pragma unroll
        for (int j4 = 0; j4 < 16; ++j4) {
            const int j = j4 * 4;
            float4 v0 = *(const float4*)&Vs[(j + 0) * 64 + 4 * tx];
            float4 v1 = *(const float4*)&Vs[(j + 1) * 64 + 4 * tx];
            float4 v2 = *(const float4*)&Vs[(j + 2) * 64 + 4 * tx];
            float4 v3 = *(const float4*)&Vs[(j + 3) * 64 + 4 * tx];
#pragma unroll
            for (int i = 0; i < 4; ++i) {
                float4 p = *(const float4*)&Ps[(4 * ty + i) * 64 + j];
                o[i].x += p.x * v0.x + p.y * v1.x + p.z * v2.x + p.w * v3.x;
                o[i].y += p.x * v0.y + p.y * v1.y + p.z * v2.y + p.w * v3.y;
                o[i].z += p.x * v0.z + p.y * v1.z + p.z * v2.z + p.w * v3.z;
                o[i].w += p.x * v0.w + p.y * v1.w + p.z * v2.w + p.w * v3.w;
            }
        }
    }

#pragma unroll
    for (int i = 0; i < 4; ++i) {
        const float inv = 1.0f / lrow[i];
        uint32_t h01, l01, h23, l23;
        split2(o[i].x * inv, o[i].y * inv, h01, l01);
        split2(o[i].z * inv, o[i].w * inv, h23, l23);
        const size_t base =
            ((size_t)n * LSEQ + l0 + 4 * ty + i) * EDIM + h * 64 + 4 * tx;
        *(uint2*)&g_atth[base] = make_uint2(h01, h23);
        *(uint2*)&g_attl[base] = make_uint2(l01, l23);
    }
}

extern "C" void kernel_launch(void* const* d_in, const int* in_sizes, int n_in,
                              void* d_out, int out_size)
{
    const float* x = (const float*)d_in[0];
    const float* W[7] = {(const float*)d_in[1], (const float*)d_in[2],
                         (const float*)d_in[3], (const float*)d_in[4],
                         (const float*)d_in[5], (const float*)d_in[6],
                         (const float*)d_in[7]};
    float* outp = (float*)d_out;

    cudaFuncSetAttribute(k_gemm<0>, cudaFuncAttributeMaxDynamicSharedMemorySize, DSM);
    cudaFuncSetAttribute(k_gemm<1>, cudaFuncAttributeMaxDynamicSharedMemorySize, DSM);

    __nv_bfloat16 *xh, *xl, *wh, *wl, *tmph, *tmpl, *atth, *attl;
    float* qkv;
    cudaGetSymbolAddress((void**)&xh, g_xh);   cudaGetSymbolAddress((void**)&xl, g_xl);
    cudaGetSymbolAddress((void**)&wh, g_wh);   cudaGetSymbolAddress((void**)&wl, g_wl);
    cudaGetSymbolAddress((void**)&tmph, g_tmph); cudaGetSymbolAddress((void**)&tmpl, g_tmpl);
    cudaGetSymbolAddress((void**)&atth, g_atth); cudaGetSymbolAddress((void**)&attl, g_attl);
    cudaGetSymbolAddress((void**)&qkv, g_qkv);

    // input conversion: x + 7 weights -> hi/lo bf16 planes
    k_cvt<<<(MTOK * EDIM / 4 + 255) / 256, 256>>>((const float4*)x, (uint2*)xh,
                                                  (uint2*)xl, MTOK * EDIM / 4);
    for (int w = 0; w < 7; ++w)
        k_cvt<<<1024, 256>>>((const float4*)W[w],
                             (uint2*)(wh + (size_t)w * 1048576u),
                             (uint2*)(wl + (size_t)w * 1048576u), 262144);

    // stage1: tmp[:, z*1024:] = x @ Wz^T  (bf16 hi/lo out)
    k_gemm<1><<<dim3(8, 64, 3), 256, DSM>>>(xh, xl, EDIM, 0, wh, wl,
                                            nullptr, tmph, tmpl, QKVC, 1024);
    // stage2: qkv[:, z*1024:] = tmp_z @ Wzp^T  (fp32 out)
    k_gemm<0><<<dim3(8, 64, 3), 256, DSM>>>(tmph, tmpl, QKVC, 1024,
                                            wh + 3u * 1048576u, wl + 3u * 1048576u,
                                            qkv, nullptr, nullptr, QKVC, 1024);
    k_att<<<dim3(LSEQ / 64, NB * NH), 256>>>();
    // out = att @ Wout^T  (fp32 out)
    k_gemm<0><<<dim3(8, 64, 1), 256, DSM>>>(atth, attl, EDIM, 0,
                                            wh + 6u * 1048576u, wl + 6u * 1048576u,
                                            outp, nullptr, nullptr, EDIM, 0);
}

// round 8
// speedup vs baseline: 1.1893x; 1.1293x over previous
#include <cuda_runtime.h>
#include <cuda_fp16.h>
#include <cstdint>

#define EDIM 1024
#define LSEQ 2048
#define NB   4
#define NH   16
#define MTOK 8192
#define QKVC 3072

// fp16 hi/lo planes + fp32 qkv scratch (allocation-free rule: __device__ globals)
__device__ __half g_xh[(size_t)MTOK * EDIM], g_xl[(size_t)MTOK * EDIM];
__device__ __half g_wh[7u * 1048576u];
__device__ __half g_tmph[(size_t)MTOK * QKVC], g_tmpl[(size_t)MTOK * QKVC];
__device__ float  g_qkv[(size_t)MTOK * QKVC];
__device__ __half g_atth[(size_t)MTOK * EDIM], g_attl[(size_t)MTOK * EDIM];

// ---- helpers --------------------------------------------------------------
__device__ __forceinline__ uint32_t smem_u32(const void* p) {
    uint32_t a;
    asm("{ .reg .u64 t; cvta.to.shared.u64 t, %1; cvt.u32.u64 %0, t; }"
        : "=r"(a) : "l"(p));
    return a;
}
// (a,b) fp32 -> packed fp16 hi pair + fp16 residual pair (lo = x - hi, exact-ish)
__device__ __forceinline__ void split2h(float a, float b, uint32_t& hi, uint32_t& lo) {
    asm("cvt.rn.f16x2.f32 %0, %1, %2;" : "=r"(hi) : "f"(b), "f"(a));
    __half2 h = *reinterpret_cast<__half2*>(&hi);
    float ar = a - __half2float(__low2half(h));
    float br = b - __half2float(__high2half(h));
    asm("cvt.rn.f16x2.f32 %0, %1, %2;" : "=r"(lo) : "f"(br), "f"(ar));
}
__device__ __forceinline__ uint32_t pack2h(float a, float b) {
    uint32_t r;
    asm("cvt.rn.f16x2.f32 %0, %1, %2;" : "=r"(r) : "f"(b), "f"(a));
    return r;
}
__device__ __forceinline__ void ldsm4(uint32_t* r, uint32_t a) {
    asm volatile("ldmatrix.sync.aligned.m8n8.x4.shared.b16 {%0,%1,%2,%3}, [%4];"
                 : "=r"(r[0]), "=r"(r[1]), "=r"(r[2]), "=r"(r[3]) : "r"(a));
}
__device__ __forceinline__ void mma_f16(float* c, const uint32_t* a,
                                        uint32_t b0, uint32_t b1) {
    asm volatile("mma.sync.aligned.m16n8k16.row.col.f32.f16.f16.f32 "
                 "{%0,%1,%2,%3}, {%4,%5,%6,%7}, {%8,%9}, {%0,%1,%2,%3};"
                 : "+f"(c[0]), "+f"(c[1]), "+f"(c[2]), "+f"(c[3])
                 : "r"(a[0]), "r"(a[1]), "r"(a[2]), "r"(a[3]), "r"(b0), "r"(b1));
}
__device__ __forceinline__ void cpa16(uint32_t d, const void* s) {
    asm volatile("cp.async.cg.shared.global [%0], [%1], 16;" :: "r"(d), "l"(s)
                 : "memory");
}

// ---- converters -----------------------------------------------------------
__global__ void __launch_bounds__(256) k_cvt2(const float4* __restrict__ in,
                                              uint2* __restrict__ hi,
                                              uint2* __restrict__ lo, int n4)
{
    int i = blockIdx.x * blockDim.x + threadIdx.x;
    if (i >= n4) return;
    float4 v = in[i];
    uint32_t h0, l0, h1, l1;
    split2h(v.x, v.y, h0, l0);
    split2h(v.z, v.w, h1, l1);
    hi[i] = make_uint2(h0, h1);
    lo[i] = make_uint2(l0, l1);
}
__global__ void __launch_bounds__(256) k_cvt1(const float4* __restrict__ in,
                                              uint2* __restrict__ hi, int n4)
{
    int i = blockIdx.x * blockDim.x + threadIdx.x;
    if (i >= n4) return;
    float4 v = in[i];
    hi[i] = make_uint2(pack2h(v.x, v.y), pack2h(v.z, v.w));
}

// ---- split-fp16 mma.sync GEMM: C = (Ah+Al) * Bh^T -------------------------
// Tile 128x128, K-slab 32, 2-stage cp.async. smem rows padded to 80B.
// Planes per slab: Ah | Al | Bh. OUT: 0 = fp32 C, 1 = fp16 hi/lo C.
#define RP    80
#define PLANE 10240   /* 128*80 */
#define BUF   30720   /* 3 planes */
#define DSM   61440

template <int OUT>
__global__ void __launch_bounds__(256, 2) k_gemm(
    const __half* __restrict__ Ah, const __half* __restrict__ Al,
    int lda, int aoff,
    const __half* __restrict__ Bh,
    float* __restrict__ Cf, __half* __restrict__ Ch, __half* __restrict__ Cl,
    int ldc, int coff)
{
    extern __shared__ __align__(16) char sm[];
    const int tid = threadIdx.x;
    const int lane = tid & 31, wid = tid >> 5;
    const int wm = wid & 1, wn = wid >> 1;        // warp grid 2(m) x 4(n)
    const int z = blockIdx.z;
    const int m0 = blockIdx.y * 128, n0 = blockIdx.x * 128;

    const __half* Azh = Ah + (size_t)z * aoff;
    const __half* Azl = Al + (size_t)z * aoff;
    const __half* Bzh = Bh + (size_t)z * 1048576u;

    const int row = tid >> 1, half = tid & 1;     // loader mapping
    const __half* pAh = Azh + (size_t)(m0 + row) * lda + half * 16;
    const __half* pAl = Azl + (size_t)(m0 + row) * lda + half * 16;
    const __half* pBh = Bzh + (size_t)(n0 + row) * 1024 + half * 16;
    const uint32_t sb = smem_u32(sm);
    const uint32_t drow = (uint32_t)row * RP + half * 32;

    auto load_slab = [&](int buf, int kt) {
        const uint32_t d = sb + buf * BUF + drow;
        const int ko = kt * 32;
        cpa16(d,                 pAh + ko); cpa16(d + 16,             pAh + ko + 8);
        cpa16(d + PLANE,         pAl + ko); cpa16(d + PLANE + 16,     pAl + ko + 8);
        cpa16(d + 2 * PLANE,     pBh + ko); cpa16(d + 2 * PLANE + 16, pBh + ko + 8);
        asm volatile("cp.async.commit_group;" ::: "memory");
    };

    float acc[4][4][4];
#pragma unroll
    for (int i = 0; i < 4; ++i)
#pragma unroll
        for (int j = 0; j < 4; ++j)
#pragma unroll
            for (int r = 0; r < 4; ++r) acc[i][j][r] = 0.f;

    load_slab(0, 0);
    load_slab(1, 1);

    const uint32_t a_base = (uint32_t)(wm * 64 + (lane & 15)) * RP + (lane >> 4) * 16;
    const uint32_t b_base = 2 * PLANE + (uint32_t)(wn * 32 + (lane & 15)) * RP
                            + (lane >> 4) * 16;

    for (int kt = 0; kt < 32; ++kt) {
        if (kt < 30) asm volatile("cp.async.wait_group 1;" ::: "memory");
        else         asm volatile("cp.async.wait_group 0;" ::: "memory");
        __syncthreads();
        const uint32_t bufb = sb + (kt & 1) * BUF;
#pragma unroll
        for (int s = 0; s < 2; ++s) {              // two k16 steps per slab
            const uint32_t stepb = bufb + s * 32;
            uint32_t ah[4][4], bh[2][4];
#pragma unroll
            for (int mi = 0; mi < 4; ++mi) ldsm4(ah[mi], stepb + a_base + mi * 1280);
#pragma unroll
            for (int p = 0; p < 2; ++p) ldsm4(bh[p], stepb + b_base + p * 1280);
#pragma unroll
            for (int mi = 0; mi < 4; ++mi)
#pragma unroll
                for (int p = 0; p < 2; ++p) {      // Ah * Bh
                    mma_f16(acc[mi][2 * p],     ah[mi], bh[p][0], bh[p][2]);
                    mma_f16(acc[mi][2 * p + 1], ah[mi], bh[p][1], bh[p][3]);
                }
#pragma unroll
            for (int mi = 0; mi < 4; ++mi) ldsm4(ah[mi], stepb + a_base + PLANE + mi * 1280);
#pragma unroll
            for (int mi = 0; mi < 4; ++mi)
#pragma unroll
                for (int p = 0; p < 2; ++p) {      // Al * Bh
                    mma_f16(acc[mi][2 * p],     ah[mi], bh[p][0], bh[p][2]);
                    mma_f16(acc[mi][2 * p + 1], ah[mi], bh[p][1], bh[p][3]);
                }
        }
        __syncthreads();
        if (kt + 2 < 32) load_slab(kt & 1, kt + 2);
    }

    const int t4 = lane >> 2, t2 = lane & 3;
#pragma unroll
    for (int mi = 0; mi < 4; ++mi) {
        const int r0 = m0 + wm * 64 + mi * 16 + t4;
#pragma unroll
        for (int nj = 0; nj < 4; ++nj) {
            const int cc = n0 + wn * 32 + (nj >> 1) * 16 + (nj & 1) * 8 + 2 * t2;
            const float* c = acc[mi][nj];
            const size_t o = (size_t)r0 * ldc + (size_t)z * coff + cc;
            if (OUT == 0) {
                *(float2*)&Cf[o]           = make_float2(c[0], c[1]);
                *(float2*)&Cf[o + 8 * ldc] = make_float2(c[2], c[3]);
            } else {
                uint32_t h, l;
                split2h(c[0], c[1], h, l);
                *(uint32_t*)&Ch[o] = h;           *(uint32_t*)&Cl[o] = l;
                split2h(c[2], c[3], h, l);
                *(uint32_t*)&Ch[o + 8 * ldc] = h; *(uint32_t*)&Cl[o + 8 * ldc] = l;
            }
        }
    }
}

// ---- flash attention fp32 (R3-proven), epilogue emits fp16 hi/lo ----------
__global__ void __launch_bounds__(256) k_att()
{
    __shared__ float Qs[64 * 64];
    __shared__ float KT[64 * 64];
    __shared__ float Vs[64 * 64];
    float* Ps = KT;

    const int tid = threadIdx.x;
    const int tx = tid & 15, ty = tid >> 4;
    const int n = blockIdx.y >> 4, h = blockIdx.y & 15;
    const int l0 = blockIdx.x * 64;

    const float* qb = g_qkv + ((size_t)n * LSEQ + l0) * QKVC + h * 64;
    const float* kb = g_qkv + (size_t)n * LSEQ * QKVC + 1024 + h * 64;
    const float* vb = kb + 1024;

    {
        const int c = tx * 4;
#pragma unroll
        for (int m = ty; m < 64; m += 16) {
            float4 v = *(const float4*)(qb + (size_t)m * QKVC + c);
            v.x *= 0.125f; v.y *= 0.125f; v.z *= 0.125f; v.w *= 0.125f;
            *(float4*)&Qs[m * 64 + c] = v;
        }
    }

    float4 o[4];
    float mrow[4], lrow[4];
#pragma unroll
    for (int i = 0; i < 4; ++i) {
        o[i] = make_float4(0.f, 0.f, 0.f, 0.f);
        mrow[i] = -3.0e38f; lrow[i] = 0.f;
    }

    for (int it = 0; it < LSEQ / 64; ++it) {
        const int lk = it * 64;
        __syncthreads();
        {
            const int kk4 = tx;
#pragma unroll
            for (int j = ty; j < 64; j += 16) {
                float4 kv = *(const float4*)(kb + (size_t)(lk + j) * QKVC + kk4 * 4);
                const int colb = 4 * ((j >> 2) ^ kk4) + (j & 3);
                KT[(4 * kk4 + 0) * 64 + colb] = kv.x;
                KT[(4 * kk4 + 1) * 64 + colb] = kv.y;
                KT[(4 * kk4 + 2) * 64 + colb] = kv.z;
                KT[(4 * kk4 + 3) * 64 + colb] = kv.w;
                *(float4*)&Vs[j * 64 + kk4 * 4] =
                    *(const float4*)(vb + (size_t)(lk + j) * QKVC + kk4 * 4);
            }
        }
        __syncthreads();

        float4 s[4];
#pragma unroll
        for (int i = 0; i < 4; ++i) s[i] = make_float4(0.f, 0.f, 0.f, 0.f);
#pragma unroll
        for (int k4 = 0; k4 < 16; ++k4) {
            const int kk = k4 * 4;
            const int pc = 4 * (tx ^ k4);
            float4 t0 = *(const float4*)&KT[(kk + 0) * 64 + pc];
            float4 t1 = *(const float4*)&KT[(kk + 1) * 64 + pc];
            float4 t2 = *(const float4*)&KT[(kk + 2) * 64 + pc];
            float4 t3 = *(const float4*)&KT[(kk + 3) * 64 + pc];
#pragma unroll
            for (int i = 0; i < 4; ++i) {
                float4 q = *(const float4*)&Qs[(4 * ty + i) * 64 + kk];
                s[i].x += q.x * t0.x + q.y * t1.x + q.z * t2.x + q.w * t3.x;
                s[i].y += q.x * t0.y + q.y * t1.y + q.z * t2.y + q.w * t3.y;
                s[i].z += q.x * t0.z + q.y * t1.z + q.z * t2.z + q.w * t3.z;
                s[i].w += q.x * t0.w + q.y * t1.w + q.z * t2.w + q.w * t3.w;
            }
        }
        __syncthreads();

#pragma unroll
        for (int i = 0; i < 4; ++i) {
            float rm = fmaxf(fmaxf(s[i].x, s[i].y), fmaxf(s[i].z, s[i].w));
#pragma unroll
            for (int off = 8; off >= 1; off >>= 1)
                rm = fmaxf(rm, __shfl_xor_sync(0xffffffffu, rm, off));
            const float mn = fmaxf(mrow[i], rm);
            const float al = __expf(mrow[i] - mn);
            mrow[i] = mn;
            s[i].x = __expf(s[i].x - mn); s[i].y = __expf(s[i].y - mn);
            s[i].z = __expf(s[i].z - mn); s[i].w = __expf(s[i].w - mn);
            float rs = s[i].x + s[i].y + s[i].z + s[i].w;
#pragma unroll
            for (int off = 8; off >= 1; off >>= 1)
                rs += __shfl_xor_sync(0xffffffffu, rs, off);
            lrow[i] = lrow[i] * al + rs;
            o[i].x *= al; o[i].y *= al; o[i].z *= al; o[i].w *= al;
            *(float4*)&Ps[(4 * ty + i) * 64 + 4 * tx] = s[i];
        }
        __syncthreads();

#pragma unroll
        for (int j4 = 0; j4 < 16; ++j4) {
            const int j = j4 * 4;
            float4 v0 = *(const float4*)&Vs[(j + 0) * 64 + 4 * tx];
            float4 v1 = *(const float4*)&Vs[(j + 1) * 64 + 4 * tx];
            float4 v2 = *(const float4*)&Vs[(j + 2) * 64 + 4 * tx];
            float4 v3 = *(const float4*)&Vs[(j + 3) * 64 + 4 * tx];
#pragma unroll
            for (int i = 0; i < 4; ++i) {
                float4 p = *(const float4*)&Ps[(4 * ty + i) * 64 + j];
                o[i].x += p.x * v0.x + p.y * v1.x + p.z * v2.x + p.w * v3.x;
                o[i].y += p.x * v0.y + p.y * v1.y + p.z * v2.y + p.w * v3.y;
                o[i].z += p.x * v0.z + p.y * v1.z + p.z * v2.z + p.w * v3.z;
                o[i].w += p.x * v0.w + p.y * v1.w + p.z * v2.w + p.w * v3.w;
            }
        }
    }

#pragma unroll
    for (int i = 0; i < 4; ++i) {
        const float inv = 1.0f / lrow[i];
        uint32_t h01, l01, h23, l23;
        split2h(o[i].x * inv, o[i].y * inv, h01, l01);
        split2h(o[i].z * inv, o[i].w * inv, h23, l23);
        const size_t base =
            ((size_t)n * LSEQ + l0 + 4 * ty + i) * EDIM + h * 64 + 4 * tx;
        *(uint2*)&g_atth[base] = make_uint2(h01, h23);
        *(uint2*)&g_attl[base] = make_uint2(l01, l23);
    }
}

extern "C" void kernel_launch(void* const* d_in, const int* in_sizes, int n_in,
                              void* d_out, int out_size)
{
    const float* x = (const float*)d_in[0];
    const float* W[7] = {(const float*)d_in[1], (const float*)d_in[2],
                         (const float*)d_in[3], (const float*)d_in[4],
                         (const float*)d_in[5], (const float*)d_in[6],
                         (const float*)d_in[7]};
    float* outp = (float*)d_out;

    cudaFuncSetAttribute(k_gemm<0>, cudaFuncAttributeMaxDynamicSharedMemorySize, DSM);
    cudaFuncSetAttribute(k_gemm<1>, cudaFuncAttributeMaxDynamicSharedMemorySize, DSM);

    __half *xh, *xl, *wh, *tmph, *tmpl, *atth, *attl;
    float* qkv;
    cudaGetSymbolAddress((void**)&xh, g_xh);     cudaGetSymbolAddress((void**)&xl, g_xl);
    cudaGetSymbolAddress((void**)&wh, g_wh);
    cudaGetSymbolAddress((void**)&tmph, g_tmph); cudaGetSymbolAddress((void**)&tmpl, g_tmpl);
    cudaGetSymbolAddress((void**)&atth, g_atth); cudaGetSymbolAddress((void**)&attl, g_attl);
    cudaGetSymbolAddress((void**)&qkv, g_qkv);

    // conversions: x -> hi/lo planes; weights -> hi plane only
    k_cvt2<<<(MTOK * EDIM / 4 + 255) / 256, 256>>>((const float4*)x, (uint2*)xh,
                                                   (uint2*)xl, MTOK * EDIM / 4);
    for (int w = 0; w < 7; ++w)
        k_cvt1<<<1024, 256>>>((const float4*)W[w],
                              (uint2*)(wh + (size_t)w * 1048576u), 262144);

    // stage1: tmp[:, z*1024:] = x @ Wz^T  (fp16 hi/lo out)
    k_gemm<1><<<dim3(8, 64, 3), 256, DSM>>>(xh, xl, EDIM, 0, wh,
                                            nullptr, tmph, tmpl, QKVC, 1024);
    // stage2: qkv[:, z*1024:] = tmp_z @ Wzp^T  (fp32 out)
    k_gemm<0><<<dim3(8, 64, 3), 256, DSM>>>(tmph, tmpl, QKVC, 1024,
                                            wh + 3u * 1048576u,
                                            qkv, nullptr, nullptr, QKVC, 1024);
    k_att<<<dim3(LSEQ / 64, NB * NH), 256>>>();
    // out = att @ Wout^T  (fp32 out)
    k_gemm<0><<<dim3(8, 64, 1), 256, DSM>>>(atth, attl, EDIM, 0,
                                            wh + 6u * 1048576u,
                                            outp, nullptr, nullptr, EDIM, 0);
}

// round 10
// speedup vs baseline: 2.0881x; 1.7558x over previous
#include <cuda_runtime.h>
#include <cuda_fp16.h>
#include <cstdint>

#define EDIM 1024
#define LSEQ 2048
#define NB   4
#define NH   16
#define MTOK 8192
#define QKVC 3072

__device__ __half g_xh[(size_t)MTOK * EDIM], g_xl[(size_t)MTOK * EDIM];
__device__ __half g_wh[7u * 1048576u];
__device__ __half g_tmph[(size_t)MTOK * QKVC], g_tmpl[(size_t)MTOK * QKVC];
__device__ __half g_qkvh[(size_t)MTOK * QKVC], g_qkvl[(size_t)MTOK * QKVC];
__device__ __half g_atth[(size_t)MTOK * EDIM], g_attl[(size_t)MTOK * EDIM];

// ---- helpers --------------------------------------------------------------
__device__ __forceinline__ uint32_t smem_u32(const void* p) {
    uint32_t a;
    asm("{ .reg .u64 t; cvta.to.shared.u64 t, %1; cvt.u32.u64 %0, t; }"
        : "=r"(a) : "l"(p));
    return a;
}
__device__ __forceinline__ void split2h(float a, float b, uint32_t& hi, uint32_t& lo) {
    asm("cvt.rn.f16x2.f32 %0, %1, %2;" : "=r"(hi) : "f"(b), "f"(a));
    __half2 h = *reinterpret_cast<__half2*>(&hi);
    float ar = a - __half2float(__low2half(h));
    float br = b - __half2float(__high2half(h));
    asm("cvt.rn.f16x2.f32 %0, %1, %2;" : "=r"(lo) : "f"(br), "f"(ar));
}
__device__ __forceinline__ uint32_t pack2h(float a, float b) {
    uint32_t r;
    asm("cvt.rn.f16x2.f32 %0, %1, %2;" : "=r"(r) : "f"(b), "f"(a));
    return r;
}
__device__ __forceinline__ void ldsm4(uint32_t* r, uint32_t a) {
    asm volatile("ldmatrix.sync.aligned.m8n8.x4.shared.b16 {%0,%1,%2,%3}, [%4];"
                 : "=r"(r[0]), "=r"(r[1]), "=r"(r[2]), "=r"(r[3]) : "r"(a));
}
__device__ __forceinline__ void ldsm4t(uint32_t* r, uint32_t a) {
    asm volatile("ldmatrix.sync.aligned.m8n8.x4.trans.shared.b16 {%0,%1,%2,%3}, [%4];"
                 : "=r"(r[0]), "=r"(r[1]), "=r"(r[2]), "=r"(r[3]) : "r"(a));
}
__device__ __forceinline__ void mma_f16(float* c, const uint32_t* a,
                                        uint32_t b0, uint32_t b1) {
    asm volatile("mma.sync.aligned.m16n8k16.row.col.f32.f16.f16.f32 "
                 "{%0,%1,%2,%3}, {%4,%5,%6,%7}, {%8,%9}, {%0,%1,%2,%3};"
                 : "+f"(c[0]), "+f"(c[1]), "+f"(c[2]), "+f"(c[3])
                 : "r"(a[0]), "r"(a[1]), "r"(a[2]), "r"(a[3]), "r"(b0), "r"(b1));
}
__device__ __forceinline__ void cpa16(uint32_t d, const void* s) {
    asm volatile("cp.async.cg.shared.global [%0], [%1], 16;" :: "r"(d), "l"(s)
                 : "memory");
}

// ---- converters -----------------------------------------------------------
__global__ void __launch_bounds__(256) k_cvt2(const float4* __restrict__ in,
                                              uint2* __restrict__ hi,
                                              uint2* __restrict__ lo, int n4)
{
    int i = blockIdx.x * blockDim.x + threadIdx.x;
    if (i >= n4) return;
    float4 v = in[i];
    uint32_t h0, l0, h1, l1;
    split2h(v.x, v.y, h0, l0);
    split2h(v.z, v.w, h1, l1);
    hi[i] = make_uint2(h0, h1);
    lo[i] = make_uint2(l0, l1);
}
__global__ void __launch_bounds__(256) k_cvt1(const float4* __restrict__ in,
                                              uint2* __restrict__ hi, int n4)
{
    int i = blockIdx.x * blockDim.x + threadIdx.x;
    if (i >= n4) return;
    float4 v = in[i];
    hi[i] = make_uint2(pack2h(v.x, v.y), pack2h(v.z, v.w));
}

// ---- split-fp16 mma.sync GEMM: C = (Ah+Al) * Bh^T (proven R8 kernel) ------
#define RP    80
#define PLANE 10240
#define BUF   30720
#define DSM   61440

template <int OUT>
__global__ void __launch_bounds__(256, 2) k_gemm(
    const __half* __restrict__ Ah, const __half* __restrict__ Al,
    int lda, int aoff,
    const __half* __restrict__ Bh,
    float* __restrict__ Cf, __half* __restrict__ Ch, __half* __restrict__ Cl,
    int ldc, int coff)
{
    extern __shared__ __align__(16) char sm[];
    const int tid = threadIdx.x;
    const int lane = tid & 31, wid = tid >> 5;
    const int wm = wid & 1, wn = wid >> 1;
    const int z = blockIdx.z;
    const int m0 = blockIdx.y * 128, n0 = blockIdx.x * 128;

    const __half* Azh = Ah + (size_t)z * aoff;
    const __half* Azl = Al + (size_t)z * aoff;
    const __half* Bzh = Bh + (size_t)z * 1048576u;

    const int row = tid >> 1, half = tid & 1;
    const __half* pAh = Azh + (size_t)(m0 + row) * lda + half * 16;
    const __half* pAl = Azl + (size_t)(m0 + row) * lda + half * 16;
    const __half* pBh = Bzh + (size_t)(n0 + row) * 1024 + half * 16;
    const uint32_t sb = smem_u32(sm);
    const uint32_t drow = (uint32_t)row * RP + half * 32;

    auto load_slab = [&](int buf, int kt) {
        const uint32_t d = sb + buf * BUF + drow;
        const int ko = kt * 32;
        cpa16(d,                 pAh + ko); cpa16(d + 16,             pAh + ko + 8);
        cpa16(d + PLANE,         pAl + ko); cpa16(d + PLANE + 16,     pAl + ko + 8);
        cpa16(d + 2 * PLANE,     pBh + ko); cpa16(d + 2 * PLANE + 16, pBh + ko + 8);
        asm volatile("cp.async.commit_group;" ::: "memory");
    };

    float acc[4][4][4];
#pragma unroll
    for (int i = 0; i < 4; ++i)
#pragma unroll
        for (int j = 0; j < 4; ++j)
#pragma unroll
            for (int r = 0; r < 4; ++r) acc[i][j][r] = 0.f;

    load_slab(0, 0);
    load_slab(1, 1);

    const uint32_t a_base = (uint32_t)(wm * 64 + (lane & 15)) * RP + (lane >> 4) * 16;
    const uint32_t b_base = 2 * PLANE + (uint32_t)(wn * 32 + (lane & 15)) * RP
                            + (lane >> 4) * 16;

    for (int kt = 0; kt < 32; ++kt) {
        if (kt < 30) asm volatile("cp.async.wait_group 1;" ::: "memory");
        else         asm volatile("cp.async.wait_group 0;" ::: "memory");
        __syncthreads();
        const uint32_t bufb = sb + (kt & 1) * BUF;
#pragma unroll
        for (int s = 0; s < 2; ++s) {
            const uint32_t stepb = bufb + s * 32;
            uint32_t ah[4][4], bh[2][4];
#pragma unroll
            for (int mi = 0; mi < 4; ++mi) ldsm4(ah[mi], stepb + a_base + mi * 1280);
#pragma unroll
            for (int p = 0; p < 2; ++p) ldsm4(bh[p], stepb + b_base + p * 1280);
#pragma unroll
            for (int mi = 0; mi < 4; ++mi)
#pragma unroll
                for (int p = 0; p < 2; ++p) {
                    mma_f16(acc[mi][2 * p],     ah[mi], bh[p][0], bh[p][2]);
                    mma_f16(acc[mi][2 * p + 1], ah[mi], bh[p][1], bh[p][3]);
                }
#pragma unroll
            for (int mi = 0; mi < 4; ++mi) ldsm4(ah[mi], stepb + a_base + PLANE + mi * 1280);
#pragma unroll
            for (int mi = 0; mi < 4; ++mi)
#pragma unroll
                for (int p = 0; p < 2; ++p) {
                    mma_f16(acc[mi][2 * p],     ah[mi], bh[p][0], bh[p][2]);
                    mma_f16(acc[mi][2 * p + 1], ah[mi], bh[p][1], bh[p][3]);
                }
        }
        __syncthreads();
        if (kt + 2 < 32) load_slab(kt & 1, kt + 2);
    }

    const int t4 = lane >> 2, t2 = lane & 3;
#pragma unroll
    for (int mi = 0; mi < 4; ++mi) {
        const int r0 = m0 + wm * 64 + mi * 16 + t4;
#pragma unroll
        for (int nj = 0; nj < 4; ++nj) {
            const int cc = n0 + wn * 32 + (nj >> 1) * 16 + (nj & 1) * 8 + 2 * t2;
            const float* c = acc[mi][nj];
            const size_t o = (size_t)r0 * ldc + (size_t)z * coff + cc;
            if (OUT == 0) {
                *(float2*)&Cf[o]           = make_float2(c[0], c[1]);
                *(float2*)&Cf[o + 8 * ldc] = make_float2(c[2], c[3]);
            } else {
                uint32_t h, l;
                split2h(c[0], c[1], h, l);
                *(uint32_t*)&Ch[o] = h;           *(uint32_t*)&Cl[o] = l;
                split2h(c[2], c[3], h, l);
                *(uint32_t*)&Ch[o + 8 * ldc] = h; *(uint32_t*)&Cl[o + 8 * ldc] = l;
            }
        }
    }
}

// ---- HMMA flash attention -------------------------------------------------
// CTA = 128 Q rows of one (n,h). KV tile 128. 8 warps x 16 S-rows each.
// QK 3-term (QhKh + QlKh + QhKl), PV 2-term ((Ph+Pl)Vh), P in registers.
#define RPA   144
#define QPL   18432           /* 128*144 */
#define KVSL  55296           /* Kh|Kl|Vh planes */
#define ADSM  147456          /* 2*QPL + 2*KVSL */

__global__ void __launch_bounds__(256) k_att()
{
    extern __shared__ __align__(16) char sm[];
    const int tid = threadIdx.x;
    const int lane = tid & 31, wid = tid >> 5;
    const int n = blockIdx.y >> 4, h = blockIdx.y & 15;
    const int l0 = blockIdx.x * 128;
    const uint32_t sb = smem_u32(sm);

    const int row = tid >> 1, half = tid & 1;
    const size_t qrow = (size_t)(n * LSEQ + l0 + row) * QKVC + h * 64 + half * 32;
    const uint32_t drow = (uint32_t)row * RPA + half * 64;

    {   // Q hi/lo planes (join group 0 with first KV slab)
        const __half* sh = g_qkvh + qrow;
        const __half* sl = g_qkvl + qrow;
#pragma unroll
        for (int j = 0; j < 4; ++j) {
            cpa16(sb + drow + j * 16,       sh + j * 8);
            cpa16(sb + QPL + drow + j * 16, sl + j * 8);
        }
    }
    const size_t krow0 = (size_t)(n * LSEQ + row) * QKVC + 1024 + h * 64 + half * 32;
    auto load_kv = [&](int buf, int t) {
        const uint32_t d = sb + 2 * QPL + buf * KVSL + drow;
        const size_t src = krow0 + (size_t)t * 128 * QKVC;
#pragma unroll
        for (int j = 0; j < 4; ++j) {
            cpa16(d + j * 16,             g_qkvh + src + j * 8);           // Kh
            cpa16(d + 18432 + j * 16,     g_qkvl + src + j * 8);           // Kl
            cpa16(d + 36864 + j * 16,     g_qkvh + src + 1024 + j * 8);    // Vh
        }
        asm volatile("cp.async.commit_group;" ::: "memory");
    };
    load_kv(0, 0);
    load_kv(1, 1);

    float o[8][4];
#pragma unroll
    for (int i = 0; i < 8; ++i)
#pragma unroll
        for (int r = 0; r < 4; ++r) o[i][r] = 0.f;
    float m0 = -3.0e38f, m1 = -3.0e38f, l0s = 0.f, l1s = 0.f;

    const int wr = wid * 16;
    const uint32_t a_addr = (uint32_t)(wr + (lane & 15)) * RPA + (lane >> 4) * 16;
    const uint32_t vrow = (uint32_t)(lane & 15) * RPA + ((lane & 16) ? 16 : 0);

    for (int t = 0; t < 16; ++t) {
        if (t < 14) asm volatile("cp.async.wait_group 1;" ::: "memory");
        else        asm volatile("cp.async.wait_group 0;" ::: "memory");
        __syncthreads();
        const uint32_t KH = sb + 2 * QPL + (t & 1) * KVSL;
        const uint32_t KL = KH + 18432, VH = KH + 36864;

        float sc[16][4];
#pragma unroll
        for (int f = 0; f < 16; ++f)
#pragma unroll
            for (int r = 0; r < 4; ++r) sc[f][r] = 0.f;

#pragma unroll
        for (int s = 0; s < 4; ++s) {
            uint32_t aqh[4], aql[4];
            ldsm4(aqh, sb + a_addr + s * 32);
            ldsm4(aql, sb + QPL + a_addr + s * 32);
#pragma unroll
            for (int nb = 0; nb < 8; ++nb) {
                const uint32_t kaddr = (uint32_t)(nb * 16 + (lane & 15)) * RPA
                                       + s * 32 + (lane >> 4) * 16;
                uint32_t bh[4], bl[4];
                ldsm4(bh, KH + kaddr);
                mma_f16(sc[2 * nb],     aqh, bh[0], bh[2]);
                mma_f16(sc[2 * nb + 1], aqh, bh[1], bh[3]);
                mma_f16(sc[2 * nb],     aql, bh[0], bh[2]);
                mma_f16(sc[2 * nb + 1], aql, bh[1], bh[3]);
                ldsm4(bl, KL + kaddr);
                mma_f16(sc[2 * nb],     aqh, bl[0], bl[2]);
                mma_f16(sc[2 * nb + 1], aqh, bl[1], bl[3]);
            }
        }

        // online softmax (rows r0 = c0/c1, r1 = c2/c3; reduce over 4 t2-lanes)
        float rm0 = -3.0e38f, rm1 = -3.0e38f;
#pragma unroll
        for (int f = 0; f < 16; ++f) {
#pragma unroll
            for (int r = 0; r < 4; ++r) sc[f][r] *= 0.125f;
            rm0 = fmaxf(rm0, fmaxf(sc[f][0], sc[f][1]));
            rm1 = fmaxf(rm1, fmaxf(sc[f][2], sc[f][3]));
        }
#pragma unroll
        for (int off = 1; off <= 2; off <<= 1) {
            rm0 = fmaxf(rm0, __shfl_xor_sync(0xffffffffu, rm0, off));
            rm1 = fmaxf(rm1, __shfl_xor_sync(0xffffffffu, rm1, off));
        }
        const float mn0 = fmaxf(m0, rm0), mn1 = fmaxf(m1, rm1);
        const float al0 = __expf(m0 - mn0), al1 = __expf(m1 - mn1);
        m0 = mn0; m1 = mn1;
        float rs0 = 0.f, rs1 = 0.f;
#pragma unroll
        for (int f = 0; f < 16; ++f) {
            sc[f][0] = __expf(sc[f][0] - mn0); sc[f][1] = __expf(sc[f][1] - mn0);
            sc[f][2] = __expf(sc[f][2] - mn1); sc[f][3] = __expf(sc[f][3] - mn1);
            rs0 += sc[f][0] + sc[f][1];
            rs1 += sc[f][2] + sc[f][3];
        }
#pragma unroll
        for (int off = 1; off <= 2; off <<= 1) {
            rs0 += __shfl_xor_sync(0xffffffffu, rs0, off);
            rs1 += __shfl_xor_sync(0xffffffffu, rs1, off);
        }
        l0s = l0s * al0 + rs0;
        l1s = l1s * al1 + rs1;
#pragma unroll
        for (int i = 0; i < 8; ++i) {
            o[i][0] *= al0; o[i][1] *= al0; o[i][2] *= al1; o[i][3] *= al1;
        }

        // PV: P fragments built in registers from sc
#pragma unroll
        for (int g = 0; g < 8; ++g) {
            uint32_t ap[4], alp[4];
            split2h(sc[2 * g][0],     sc[2 * g][1],     ap[0], alp[0]);
            split2h(sc[2 * g][2],     sc[2 * g][3],     ap[1], alp[1]);
            split2h(sc[2 * g + 1][0], sc[2 * g + 1][1], ap[2], alp[2]);
            split2h(sc[2 * g + 1][2], sc[2 * g + 1][3], ap[3], alp[3]);
#pragma unroll
            for (int nbp = 0; nbp < 4; ++nbp) {
                uint32_t bv[4];
                ldsm4t(bv, VH + vrow + (uint32_t)g * 16 * RPA + nbp * 32);
                mma_f16(o[2 * nbp],     ap,  bv[0], bv[1]);
                mma_f16(o[2 * nbp + 1], ap,  bv[2], bv[3]);
                mma_f16(o[2 * nbp],     alp, bv[0], bv[1]);
                mma_f16(o[2 * nbp + 1], alp, bv[2], bv[3]);
            }
        }
        __syncthreads();
        if (t + 2 < 16) load_kv(t & 1, t + 2);
    }

    // epilogue: normalize + fp16 hi/lo store
    const float inv0 = 1.0f / l0s, inv1 = 1.0f / l1s;
    const int t4 = lane >> 2, t2 = lane & 3;
    const size_t r0 = (size_t)(n * LSEQ + l0 + wr + t4) * EDIM + h * 64 + 2 * t2;
    const size_t r1 = r0 + 8 * EDIM;
#pragma unroll
    for (int nb = 0; nb < 8; ++nb) {
        uint32_t hh, ll;
        split2h(o[nb][0] * inv0, o[nb][1] * inv0, hh, ll);
        *(uint32_t*)&g_atth[r0 + 8 * nb] = hh;
        *(uint32_t*)&g_attl[r0 + 8 * nb] = ll;
        split2h(o[nb][2] * inv1, o[nb][3] * inv1, hh, ll);
        *(uint32_t*)&g_atth[r1 + 8 * nb] = hh;
        *(uint32_t*)&g_attl[r1 + 8 * nb] = ll;
    }
}

extern "C" void kernel_launch(void* const* d_in, const int* in_sizes, int n_in,
                              void* d_out, int out_size)
{
    const float* x = (const float*)d_in[0];
    const float* W[7] = {(const float*)d_in[1], (const float*)d_in[2],
                         (const float*)d_in[3], (const float*)d_in[4],
                         (const float*)d_in[5], (const float*)d_in[6],
                         (const float*)d_in[7]};
    float* outp = (float*)d_out;

    cudaFuncSetAttribute(k_gemm<0>, cudaFuncAttributeMaxDynamicSharedMemorySize, DSM);
    cudaFuncSetAttribute(k_gemm<1>, cudaFuncAttributeMaxDynamicSharedMemorySize, DSM);
    cudaFuncSetAttribute(k_att, cudaFuncAttributeMaxDynamicSharedMemorySize, ADSM);

    __half *xh, *xl, *wh, *tmph, *tmpl, *qkvh, *qkvl, *atth, *attl;
    cudaGetSymbolAddress((void**)&xh, g_xh);     cudaGetSymbolAddress((void**)&xl, g_xl);
    cudaGetSymbolAddress((void**)&wh, g_wh);
    cudaGetSymbolAddress((void**)&tmph, g_tmph); cudaGetSymbolAddress((void**)&tmpl, g_tmpl);
    cudaGetSymbolAddress((void**)&qkvh, g_qkvh); cudaGetSymbolAddress((void**)&qkvl, g_qkvl);
    cudaGetSymbolAddress((void**)&atth, g_atth); cudaGetSymbolAddress((void**)&attl, g_attl);

    k_cvt2<<<(MTOK * EDIM / 4 + 255) / 256, 256>>>((const float4*)x, (uint2*)xh,
                                                   (uint2*)xl, MTOK * EDIM / 4);
    for (int w = 0; w < 7; ++w)
        k_cvt1<<<1024, 256>>>((const float4*)W[w],
                              (uint2*)(wh + (size_t)w * 1048576u), 262144);

    // stage1: tmp = x @ W{q,k,v}^T (fp16 hi/lo)
    k_gemm<1><<<dim3(8, 64, 3), 256, DSM>>>(xh, xl, EDIM, 0, wh,
                                            nullptr, tmph, tmpl, QKVC, 1024);
    // stage2: qkv = tmp @ W{qp,kp,vp}^T (fp16 hi/lo)
    k_gemm<1><<<dim3(8, 64, 3), 256, DSM>>>(tmph, tmpl, QKVC, 1024,
                                            wh + 3u * 1048576u,
                                            nullptr, qkvh, qkvl, QKVC, 1024);
    k_att<<<dim3(LSEQ / 128, NB * NH), 256, ADSM>>>();
    // out = att @ Wout^T (fp32)
    k_gemm<0><<<dim3(8, 64, 1), 256, DSM>>>(atth, attl, EDIM, 0,
                                            wh + 6u * 1048576u,
                                            outp, nullptr, nullptr, EDIM, 0);
}

// round 11
// speedup vs baseline: 2.5916x; 1.2412x over previous
#include <cuda_runtime.h>
#include <cuda_fp16.h>
#include <cstdint>

#define EDIM 1024
#define LSEQ 2048
#define NB   4
#define NH   16
#define MTOK 8192
#define QKVC 3072
#define WSZ  1048576u

__device__ __half g_xh[(size_t)MTOK * EDIM], g_xl[(size_t)MTOK * EDIM];
__device__ __half g_wph[3u * WSZ], g_wpl[3u * WSZ];     // Wqp/Wkp/Wvp hi/lo
__device__ __half g_wth[3u * WSZ], g_wtl[3u * WSZ];     // Wq^T/Wk^T/Wv^T hi/lo
__device__ __half g_wch[3u * WSZ], g_wcl[3u * WSZ];     // Wc = Wp@W hi/lo
__device__ __half g_wouth[WSZ];
__device__ __half g_qkvh[(size_t)MTOK * QKVC], g_qkvl[(size_t)MTOK * QKVC];
__device__ __half g_atth[(size_t)MTOK * EDIM], g_attl[(size_t)MTOK * EDIM];

// ---- helpers --------------------------------------------------------------
__device__ __forceinline__ uint32_t smem_u32(const void* p) {
    uint32_t a;
    asm("{ .reg .u64 t; cvta.to.shared.u64 t, %1; cvt.u32.u64 %0, t; }"
        : "=r"(a) : "l"(p));
    return a;
}
__device__ __forceinline__ void split2h(float a, float b, uint32_t& hi, uint32_t& lo) {
    asm("cvt.rn.f16x2.f32 %0, %1, %2;" : "=r"(hi) : "f"(b), "f"(a));
    __half2 h = *reinterpret_cast<__half2*>(&hi);
    float ar = a - __half2float(__low2half(h));
    float br = b - __half2float(__high2half(h));
    asm("cvt.rn.f16x2.f32 %0, %1, %2;" : "=r"(lo) : "f"(br), "f"(ar));
}
__device__ __forceinline__ uint32_t pack2h(float a, float b) {
    uint32_t r;
    asm("cvt.rn.f16x2.f32 %0, %1, %2;" : "=r"(r) : "f"(b), "f"(a));
    return r;
}
__device__ __forceinline__ void ldsm4(uint32_t* r, uint32_t a) {
    asm volatile("ldmatrix.sync.aligned.m8n8.x4.shared.b16 {%0,%1,%2,%3}, [%4];"
                 : "=r"(r[0]), "=r"(r[1]), "=r"(r[2]), "=r"(r[3]) : "r"(a));
}
__device__ __forceinline__ void ldsm4t(uint32_t* r, uint32_t a) {
    asm volatile("ldmatrix.sync.aligned.m8n8.x4.trans.shared.b16 {%0,%1,%2,%3}, [%4];"
                 : "=r"(r[0]), "=r"(r[1]), "=r"(r[2]), "=r"(r[3]) : "r"(a));
}
__device__ __forceinline__ void mma_f16(float* c, const uint32_t* a,
                                        uint32_t b0, uint32_t b1) {
    asm volatile("mma.sync.aligned.m16n8k16.row.col.f32.f16.f16.f32 "
                 "{%0,%1,%2,%3}, {%4,%5,%6,%7}, {%8,%9}, {%0,%1,%2,%3};"
                 : "+f"(c[0]), "+f"(c[1]), "+f"(c[2]), "+f"(c[3])
                 : "r"(a[0]), "r"(a[1]), "r"(a[2]), "r"(a[3]), "r"(b0), "r"(b1));
}
__device__ __forceinline__ void cpa16(uint32_t d, const void* s) {
    asm volatile("cp.async.cg.shared.global [%0], [%1], 16;" :: "r"(d), "l"(s)
                 : "memory");
}

// ---- converters -----------------------------------------------------------
__global__ void __launch_bounds__(256) k_cvt2(const float4* __restrict__ in,
                                              uint2* __restrict__ hi,
                                              uint2* __restrict__ lo, int n4)
{
    int i = blockIdx.x * blockDim.x + threadIdx.x;
    if (i >= n4) return;
    float4 v = in[i];
    uint32_t h0, l0, h1, l1;
    split2h(v.x, v.y, h0, l0);
    split2h(v.z, v.w, h1, l1);
    hi[i] = make_uint2(h0, h1);
    lo[i] = make_uint2(l0, l1);
}
__global__ void __launch_bounds__(256) k_cvt1(const float4* __restrict__ in,
                                              uint2* __restrict__ hi, int n4)
{
    int i = blockIdx.x * blockDim.x + threadIdx.x;
    if (i >= n4) return;
    float4 v = in[i];
    hi[i] = make_uint2(pack2h(v.x, v.y), pack2h(v.z, v.w));
}

// ---- transpose + split: W (1024x1024 fp32) -> W^T hi/lo fp16 planes -------
__global__ void __launch_bounds__(256) k_tr(const float* __restrict__ W0,
                                            const float* __restrict__ W1,
                                            const float* __restrict__ W2)
{
    __shared__ float tile[64][65];
    const int z = blockIdx.z;
    const float* W = (z == 0) ? W0 : (z == 1) ? W1 : W2;
    const int r0 = blockIdx.y * 64, c0 = blockIdx.x * 64;
    const int row = threadIdx.x >> 2, c4 = (threadIdx.x & 3) * 16;

#pragma unroll
    for (int i = 0; i < 4; ++i) {
        float4 v = *(const float4*)(W + (size_t)(r0 + row) * 1024 + c0 + c4 + i * 4);
        tile[row][c4 + i * 4 + 0] = v.x; tile[row][c4 + i * 4 + 1] = v.y;
        tile[row][c4 + i * 4 + 2] = v.z; tile[row][c4 + i * 4 + 3] = v.w;
    }
    __syncthreads();

    uint32_t hb[8], lb[8];
#pragma unroll
    for (int i = 0; i < 8; ++i)
        split2h(tile[c4 + 2 * i][row], tile[c4 + 2 * i + 1][row], hb[i], lb[i]);
    const size_t o = (size_t)z * WSZ + (size_t)(c0 + row) * 1024 + r0 + c4;
    *(uint4*)&g_wth[o]     = make_uint4(hb[0], hb[1], hb[2], hb[3]);
    *(uint4*)&g_wth[o + 8] = make_uint4(hb[4], hb[5], hb[6], hb[7]);
    *(uint4*)&g_wtl[o]     = make_uint4(lb[0], lb[1], lb[2], lb[3]);
    *(uint4*)&g_wtl[o + 8] = make_uint4(lb[4], lb[5], lb[6], lb[7]);
}

// ---- split-fp16 mma.sync GEMM: C = (Ah+Al)*Bh^T [+ Ah*Bl^T if BL] ---------
#define RP    80
#define PLANE 10240

template <int OUT, int BL>
__global__ void __launch_bounds__(256, 2) k_gemm(
    const __half* __restrict__ Ah, const __half* __restrict__ Al,
    int lda, int aoff,
    const __half* __restrict__ Bh, const __half* __restrict__ Bl,
    float* __restrict__ Cf, __half* __restrict__ Ch, __half* __restrict__ Cl,
    int ldc, int coff)
{
    constexpr int BUF = (3 + BL) * PLANE;
    extern __shared__ __align__(16) char sm[];
    const int tid = threadIdx.x;
    const int lane = tid & 31, wid = tid >> 5;
    const int wm = wid & 1, wn = wid >> 1;
    const int z = blockIdx.z;
    const int m0 = blockIdx.y * 128, n0 = blockIdx.x * 128;

    const __half* Azh = Ah + (size_t)z * aoff;
    const __half* Azl = Al + (size_t)z * aoff;
    const __half* Bzh = Bh + (size_t)z * WSZ;
    const __half* Bzl = BL ? (Bl + (size_t)z * WSZ) : nullptr;

    const int row = tid >> 1, half = tid & 1;
    const __half* pAh = Azh + (size_t)(m0 + row) * lda + half * 16;
    const __half* pAl = Azl + (size_t)(m0 + row) * lda + half * 16;
    const __half* pBh = Bzh + (size_t)(n0 + row) * 1024 + half * 16;
    const __half* pBl = BL ? (Bzl + (size_t)(n0 + row) * 1024 + half * 16) : nullptr;
    const uint32_t sb = smem_u32(sm);
    const uint32_t drow = (uint32_t)row * RP + half * 32;

    auto load_slab = [&](int buf, int kt) {
        const uint32_t d = sb + buf * BUF + drow;
        const int ko = kt * 32;
        cpa16(d,                 pAh + ko); cpa16(d + 16,             pAh + ko + 8);
        cpa16(d + PLANE,         pAl + ko); cpa16(d + PLANE + 16,     pAl + ko + 8);
        cpa16(d + 2 * PLANE,     pBh + ko); cpa16(d + 2 * PLANE + 16, pBh + ko + 8);
        if (BL) {
            cpa16(d + 3 * PLANE,      pBl + ko);
            cpa16(d + 3 * PLANE + 16, pBl + ko + 8);
        }
        asm volatile("cp.async.commit_group;" ::: "memory");
    };

    float acc[4][4][4];
#pragma unroll
    for (int i = 0; i < 4; ++i)
#pragma unroll
        for (int j = 0; j < 4; ++j)
#pragma unroll
            for (int r = 0; r < 4; ++r) acc[i][j][r] = 0.f;

    load_slab(0, 0);
    load_slab(1, 1);

    const uint32_t a_base = (uint32_t)(wm * 64 + (lane & 15)) * RP + (lane >> 4) * 16;
    const uint32_t b_base = 2 * PLANE + (uint32_t)(wn * 32 + (lane & 15)) * RP
                            + (lane >> 4) * 16;

    for (int kt = 0; kt < 32; ++kt) {
        if (kt < 30) asm volatile("cp.async.wait_group 1;" ::: "memory");
        else         asm volatile("cp.async.wait_group 0;" ::: "memory");
        __syncthreads();
        const uint32_t bufb = sb + (kt & 1) * BUF;
#pragma unroll
        for (int s = 0; s < 2; ++s) {
            const uint32_t stepb = bufb + s * 32;
            uint32_t ah[4][4], bh[2][4];
#pragma unroll
            for (int mi = 0; mi < 4; ++mi) ldsm4(ah[mi], stepb + a_base + mi * 1280);
#pragma unroll
            for (int p = 0; p < 2; ++p) ldsm4(bh[p], stepb + b_base + p * 1280);
#pragma unroll
            for (int mi = 0; mi < 4; ++mi)
#pragma unroll
                for (int p = 0; p < 2; ++p) {
                    mma_f16(acc[mi][2 * p],     ah[mi], bh[p][0], bh[p][2]);
                    mma_f16(acc[mi][2 * p + 1], ah[mi], bh[p][1], bh[p][3]);
                }
            if (BL) {
                uint32_t bl[2][4];
#pragma unroll
                for (int p = 0; p < 2; ++p)
                    ldsm4(bl[p], stepb + b_base + PLANE + p * 1280);
#pragma unroll
                for (int mi = 0; mi < 4; ++mi)
#pragma unroll
                    for (int p = 0; p < 2; ++p) {
                        mma_f16(acc[mi][2 * p],     ah[mi], bl[p][0], bl[p][2]);
                        mma_f16(acc[mi][2 * p + 1], ah[mi], bl[p][1], bl[p][3]);
                    }
            }
#pragma unroll
            for (int mi = 0; mi < 4; ++mi) ldsm4(ah[mi], stepb + a_base + PLANE + mi * 1280);
#pragma unroll
            for (int mi = 0; mi < 4; ++mi)
#pragma unroll
                for (int p = 0; p < 2; ++p) {
                    mma_f16(acc[mi][2 * p],     ah[mi], bh[p][0], bh[p][2]);
                    mma_f16(acc[mi][2 * p + 1], ah[mi], bh[p][1], bh[p][3]);
                }
        }
        __syncthreads();
        if (kt + 2 < 32) load_slab(kt & 1, kt + 2);
    }

    const int t4 = lane >> 2, t2 = lane & 3;
#pragma unroll
    for (int mi = 0; mi < 4; ++mi) {
        const int r0 = m0 + wm * 64 + mi * 16 + t4;
#pragma unroll
        for (int nj = 0; nj < 4; ++nj) {
            const int cc = n0 + wn * 32 + (nj >> 1) * 16 + (nj & 1) * 8 + 2 * t2;
            const float* c = acc[mi][nj];
            const size_t o = (size_t)r0 * ldc + (size_t)z * coff + cc;
            if (OUT == 0) {
                *(float2*)&Cf[o]           = make_float2(c[0], c[1]);
                *(float2*)&Cf[o + 8 * ldc] = make_float2(c[2], c[3]);
            } else {
                uint32_t h, l;
                split2h(c[0], c[1], h, l);
                *(uint32_t*)&Ch[o] = h;           *(uint32_t*)&Cl[o] = l;
                split2h(c[2], c[3], h, l);
                *(uint32_t*)&Ch[o + 8 * ldc] = h; *(uint32_t*)&Cl[o + 8 * ldc] = l;
            }
        }
    }
}

// ---- HMMA flash attention (proven R10 kernel) -----------------------------
#define RPA   144
#define QPL   18432
#define KVSL  55296
#define ADSM  147456

__global__ void __launch_bounds__(256) k_att()
{
    extern __shared__ __align__(16) char sm[];
    const int tid = threadIdx.x;
    const int lane = tid & 31, wid = tid >> 5;
    const int n = blockIdx.y >> 4, h = blockIdx.y & 15;
    const int l0 = blockIdx.x * 128;
    const uint32_t sb = smem_u32(sm);

    const int row = tid >> 1, half = tid & 1;
    const size_t qrow = (size_t)(n * LSEQ + l0 + row) * QKVC + h * 64 + half * 32;
    const uint32_t drow = (uint32_t)row * RPA + half * 64;

    {
        const __half* sh = g_qkvh + qrow;
        const __half* sl = g_qkvl + qrow;
#pragma unroll
        for (int j = 0; j < 4; ++j) {
            cpa16(sb + drow + j * 16,       sh + j * 8);
            cpa16(sb + QPL + drow + j * 16, sl + j * 8);
        }
    }
    const size_t krow0 = (size_t)(n * LSEQ + row) * QKVC + 1024 + h * 64 + half * 32;
    auto load_kv = [&](int buf, int t) {
        const uint32_t d = sb + 2 * QPL + buf * KVSL + drow;
        const size_t src = krow0 + (size_t)t * 128 * QKVC;
#pragma unroll
        for (int j = 0; j < 4; ++j) {
            cpa16(d + j * 16,         g_qkvh + src + j * 8);
            cpa16(d + 18432 + j * 16, g_qkvl + src + j * 8);
            cpa16(d + 36864 + j * 16, g_qkvh + src + 1024 + j * 8);
        }
        asm volatile("cp.async.commit_group;" ::: "memory");
    };
    load_kv(0, 0);
    load_kv(1, 1);

    float o[8][4];
#pragma unroll
    for (int i = 0; i < 8; ++i)
#pragma unroll
        for (int r = 0; r < 4; ++r) o[i][r] = 0.f;
    float m0 = -3.0e38f, m1 = -3.0e38f, l0s = 0.f, l1s = 0.f;

    const int wr = wid * 16;
    const uint32_t a_addr = (uint32_t)(wr + (lane & 15)) * RPA + (lane >> 4) * 16;
    const uint32_t vrow = (uint32_t)(lane & 15) * RPA + ((lane & 16) ? 16 : 0);

    for (int t = 0; t < 16; ++t) {
        if (t < 14) asm volatile("cp.async.wait_group 1;" ::: "memory");
        else        asm volatile("cp.async.wait_group 0;" ::: "memory");
        __syncthreads();
        const uint32_t KH = sb + 2 * QPL + (t & 1) * KVSL;
        const uint32_t KL = KH + 18432, VH = KH + 36864;

        float sc[16][4];
#pragma unroll
        for (int f = 0; f < 16; ++f)
#pragma unroll
            for (int r = 0; r < 4; ++r) sc[f][r] = 0.f;

#pragma unroll
        for (int s = 0; s < 4; ++s) {
            uint32_t aqh[4], aql[4];
            ldsm4(aqh, sb + a_addr + s * 32);
            ldsm4(aql, sb + QPL + a_addr + s * 32);
#pragma unroll
            for (int nb = 0; nb < 8; ++nb) {
                const uint32_t kaddr = (uint32_t)(nb * 16 + (lane & 15)) * RPA
                                       + s * 32 + (lane >> 4) * 16;
                uint32_t bh[4], bl[4];
                ldsm4(bh, KH + kaddr);
                mma_f16(sc[2 * nb],     aqh, bh[0], bh[2]);
                mma_f16(sc[2 * nb + 1], aqh, bh[1], bh[3]);
                mma_f16(sc[2 * nb],     aql, bh[0], bh[2]);
                mma_f16(sc[2 * nb + 1], aql, bh[1], bh[3]);
                ldsm4(bl, KL + kaddr);
                mma_f16(sc[2 * nb],     aqh, bl[0], bl[2]);
                mma_f16(sc[2 * nb + 1], aqh, bl[1], bl[3]);
            }
        }

        float rm0 = -3.0e38f, rm1 = -3.0e38f;
#pragma unroll
        for (int f = 0; f < 16; ++f) {
#pragma unroll
            for (int r = 0; r < 4; ++r) sc[f][r] *= 0.125f;
            rm0 = fmaxf(rm0, fmaxf(sc[f][0], sc[f][1]));
            rm1 = fmaxf(rm1, fmaxf(sc[f][2], sc[f][3]));
        }
#pragma unroll
        for (int off = 1; off <= 2; off <<= 1) {
            rm0 = fmaxf(rm0, __shfl_xor_sync(0xffffffffu, rm0, off));
            rm1 = fmaxf(rm1, __shfl_xor_sync(0xffffffffu, rm1, off));
        }
        const float mn0 = fmaxf(m0, rm0), mn1 = fmaxf(m1, rm1);
        const float al0 = __expf(m0 - mn0), al1 = __expf(m1 - mn1);
        m0 = mn0; m1 = mn1;
        float rs0 = 0.f, rs1 = 0.f;
#pragma unroll
        for (int f = 0; f < 16; ++f) {
            sc[f][0] = __expf(sc[f][0] - mn0); sc[f][1] = __expf(sc[f][1] - mn0);
            sc[f][2] = __expf(sc[f][2] - mn1); sc[f][3] = __expf(sc[f][3] - mn1);
            rs0 += sc[f][0] + sc[f][1];
            rs1 += sc[f][2] + sc[f][3];
        }
#pragma unroll
        for (int off = 1; off <= 2; off <<= 1) {
            rs0 += __shfl_xor_sync(0xffffffffu, rs0, off);
            rs1 += __shfl_xor_sync(0xffffffffu, rs1, off);
        }
        l0s = l0s * al0 + rs0;
        l1s = l1s * al1 + rs1;
#pragma unroll
        for (int i = 0; i < 8; ++i) {
            o[i][0] *= al0; o[i][1] *= al0; o[i][2] *= al1; o[i][3] *= al1;
        }

#pragma unroll
        for (int g = 0; g < 8; ++g) {
            uint32_t ap[4], alp[4];
            split2h(sc[2 * g][0],     sc[2 * g][1],     ap[0], alp[0]);
            split2h(sc[2 * g][2],     sc[2 * g][3],     ap[1], alp[1]);
            split2h(sc[2 * g + 1][0], sc[2 * g + 1][1], ap[2], alp[2]);
            split2h(sc[2 * g + 1][2], sc[2 * g + 1][3], ap[3], alp[3]);
#pragma unroll
            for (int nbp = 0; nbp < 4; ++nbp) {
                uint32_t bv[4];
                ldsm4t(bv, VH + vrow + (uint32_t)g * 16 * RPA + nbp * 32);
                mma_f16(o[2 * nbp],     ap,  bv[0], bv[1]);
                mma_f16(o[2 * nbp + 1], ap,  bv[2], bv[3]);
                mma_f16(o[2 * nbp],     alp, bv[0], bv[1]);
                mma_f16(o[2 * nbp + 1], alp, bv[2], bv[3]);
            }
        }
        __syncthreads();
        if (t + 2 < 16) load_kv(t & 1, t + 2);
    }

    const float inv0 = 1.0f / l0s, inv1 = 1.0f / l1s;
    const int t4 = lane >> 2, t2 = lane & 3;
    const size_t r0 = (size_t)(n * LSEQ + l0 + wr + t4) * EDIM + h * 64 + 2 * t2;
    const size_t r1 = r0 + 8 * EDIM;
#pragma unroll
    for (int nb = 0; nb < 8; ++nb) {
        uint32_t hh, ll;
        split2h(o[nb][0] * inv0, o[nb][1] * inv0, hh, ll);
        *(uint32_t*)&g_atth[r0 + 8 * nb] = hh;
        *(uint32_t*)&g_attl[r0 + 8 * nb] = ll;
        split2h(o[nb][2] * inv1, o[nb][3] * inv1, hh, ll);
        *(uint32_t*)&g_atth[r1 + 8 * nb] = hh;
        *(uint32_t*)&g_attl[r1 + 8 * nb] = ll;
    }
}

extern "C" void kernel_launch(void* const* d_in, const int* in_sizes, int n_in,
                              void* d_out, int out_size)
{
    const float* x    = (const float*)d_in[0];
    const float* Wq   = (const float*)d_in[1];
    const float* Wk   = (const float*)d_in[2];
    const float* Wv   = (const float*)d_in[3];
    const float* Wqp  = (const float*)d_in[4];
    const float* Wkp  = (const float*)d_in[5];
    const float* Wvp  = (const float*)d_in[6];
    const float* Wout = (const float*)d_in[7];
    float* outp = (float*)d_out;

    const int DSM3 = 2 * 3 * PLANE;   // 61440
    const int DSM4 = 2 * 4 * PLANE;   // 81920
    cudaFuncSetAttribute((const void*)k_gemm<0, 0>,
                         cudaFuncAttributeMaxDynamicSharedMemorySize, DSM3);
    cudaFuncSetAttribute((const void*)k_gemm<1, 0>,
                         cudaFuncAttributeMaxDynamicSharedMemorySize, DSM3);
    cudaFuncSetAttribute((const void*)k_gemm<1, 1>,
                         cudaFuncAttributeMaxDynamicSharedMemorySize, DSM4);
    cudaFuncSetAttribute((const void*)k_att,
                         cudaFuncAttributeMaxDynamicSharedMemorySize, ADSM);

    __half *xh, *xl, *wph, *wpl, *wth, *wtl, *wch, *wcl, *wouth;
    __half *qkvh, *qkvl, *atth, *attl;
    cudaGetSymbolAddress((void**)&xh, g_xh);     cudaGetSymbolAddress((void**)&xl, g_xl);
    cudaGetSymbolAddress((void**)&wph, g_wph);   cudaGetSymbolAddress((void**)&wpl, g_wpl);
    cudaGetSymbolAddress((void**)&wth, g_wth);   cudaGetSymbolAddress((void**)&wtl, g_wtl);
    cudaGetSymbolAddress((void**)&wch, g_wch);   cudaGetSymbolAddress((void**)&wcl, g_wcl);
    cudaGetSymbolAddress((void**)&wouth, g_wouth);
    cudaGetSymbolAddress((void**)&qkvh, g_qkvh); cudaGetSymbolAddress((void**)&qkvl, g_qkvl);
    cudaGetSymbolAddress((void**)&atth, g_atth); cudaGetSymbolAddress((void**)&attl, g_attl);

    // conversions / transposes
    k_cvt2<<<(MTOK * EDIM / 4 + 255) / 256, 256>>>((const float4*)x, (uint2*)xh,
                                                   (uint2*)xl, MTOK * EDIM / 4);
    k_tr<<<dim3(16, 16, 3), 256>>>(Wq, Wk, Wv);
    const float* Wp[3] = {Wqp, Wkp, Wvp};
    for (int w = 0; w < 3; ++w)
        k_cvt2<<<1024, 256>>>((const float4*)Wp[w],
                              (uint2*)(wph + (size_t)w * WSZ),
                              (uint2*)(wpl + (size_t)w * WSZ), 262144);
    k_cvt1<<<1024, 256>>>((const float4*)Wout, (uint2*)wouth, 262144);

    // combine: Wc_z = Wzp @ Wz  (3-term, fp16 hi/lo out)
    k_gemm<1, 1><<<dim3(8, 8, 3), 256, DSM4>>>(wph, wpl, 1024, WSZ, wth, wtl,
                                               nullptr, wch, wcl, 1024, WSZ);
    // qkv = x @ Wc^T  (2-term, fp16 hi/lo out)
    k_gemm<1, 0><<<dim3(8, 64, 3), 256, DSM3>>>(xh, xl, EDIM, 0, wch, nullptr,
                                                nullptr, qkvh, qkvl, QKVC, 1024);
    k_att<<<dim3(LSEQ / 128, NB * NH), 256, ADSM>>>();
    // out = att @ Wout^T  (fp32 out)
    k_gemm<0, 0><<<dim3(8, 64, 1), 256, DSM3>>>(atth, attl, EDIM, 0, wouth, nullptr,
                                                outp, nullptr, nullptr, EDIM, 0);
}

// round 13
// speedup vs baseline: 2.6374x; 1.0177x over previous
#include <cuda_runtime.h>
#include <cuda_fp16.h>
#include <cstdint>

#define EDIM 1024
#define LSEQ 2048
#define NB   4
#define NH   16
#define MTOK 8192
#define QKVC 3072
#define WSZ  1048576u

__device__ __half g_xh[(size_t)MTOK * EDIM], g_xl[(size_t)MTOK * EDIM];
__device__ __half g_wph[3u * WSZ], g_wpl[3u * WSZ];     // Wqp/Wkp/Wvp hi/lo
__device__ __half g_wth[3u * WSZ], g_wtl[3u * WSZ];     // Wq^T/Wk^T/Wv^T hi/lo
__device__ __half g_wch[3u * WSZ], g_wcl[3u * WSZ];     // Wc = Wp@W hi/lo
__device__ __half g_wouth[WSZ];
__device__ __half g_qkvh[(size_t)MTOK * QKVC], g_qkvl[(size_t)MTOK * QKVC];
__device__ __half g_atth[(size_t)MTOK * EDIM], g_attl[(size_t)MTOK * EDIM];

// ---- helpers --------------------------------------------------------------
__device__ __forceinline__ uint32_t smem_u32(const void* p) {
    uint32_t a;
    asm("{ .reg .u64 t; cvta.to.shared.u64 t, %1; cvt.u32.u64 %0, t; }"
        : "=r"(a) : "l"(p));
    return a;
}
__device__ __forceinline__ void split2h(float a, float b, uint32_t& hi, uint32_t& lo) {
    asm("cvt.rn.f16x2.f32 %0, %1, %2;" : "=r"(hi) : "f"(b), "f"(a));
    __half2 h = *reinterpret_cast<__half2*>(&hi);
    float ar = a - __half2float(__low2half(h));
    float br = b - __half2float(__high2half(h));
    asm("cvt.rn.f16x2.f32 %0, %1, %2;" : "=r"(lo) : "f"(br), "f"(ar));
}
__device__ __forceinline__ uint32_t pack2h(float a, float b) {
    uint32_t r;
    asm("cvt.rn.f16x2.f32 %0, %1, %2;" : "=r"(r) : "f"(b), "f"(a));
    return r;
}
__device__ __forceinline__ void ldsm4(uint32_t* r, uint32_t a) {
    asm volatile("ldmatrix.sync.aligned.m8n8.x4.shared.b16 {%0,%1,%2,%3}, [%4];"
                 : "=r"(r[0]), "=r"(r[1]), "=r"(r[2]), "=r"(r[3]) : "r"(a));
}
__device__ __forceinline__ void ldsm4t(uint32_t* r, uint32_t a) {
    asm volatile("ldmatrix.sync.aligned.m8n8.x4.trans.shared.b16 {%0,%1,%2,%3}, [%4];"
                 : "=r"(r[0]), "=r"(r[1]), "=r"(r[2]), "=r"(r[3]) : "r"(a));
}
__device__ __forceinline__ void mma_f16(float* c, const uint32_t* a,
                                        uint32_t b0, uint32_t b1) {
    asm volatile("mma.sync.aligned.m16n8k16.row.col.f32.f16.f16.f32 "
                 "{%0,%1,%2,%3}, {%4,%5,%6,%7}, {%8,%9}, {%0,%1,%2,%3};"
                 : "+f"(c[0]), "+f"(c[1]), "+f"(c[2]), "+f"(c[3])
                 : "r"(a[0]), "r"(a[1]), "r"(a[2]), "r"(a[3]), "r"(b0), "r"(b1));
}
__device__ __forceinline__ void cpa16(uint32_t d, const void* s) {
    asm volatile("cp.async.cg.shared.global [%0], [%1], 16;" :: "r"(d), "l"(s)
                 : "memory");
}

// ---- converters -----------------------------------------------------------
__global__ void __launch_bounds__(256) k_cvt2(const float4* __restrict__ in,
                                              uint2* __restrict__ hi,
                                              uint2* __restrict__ lo, int n4)
{
    int i = blockIdx.x * blockDim.x + threadIdx.x;
    if (i >= n4) return;
    float4 v = in[i];
    uint32_t h0, l0, h1, l1;
    split2h(v.x, v.y, h0, l0);
    split2h(v.z, v.w, h1, l1);
    hi[i] = make_uint2(h0, h1);
    lo[i] = make_uint2(l0, l1);
}
// batched 3-matrix variant (keeps launch count low so ncu -s 5 hits qkv GEMM)
__global__ void __launch_bounds__(256) k_cvt2w(const float4* __restrict__ W0,
                                               const float4* __restrict__ W1,
                                               const float4* __restrict__ W2,
                                               uint2* __restrict__ hi,
                                               uint2* __restrict__ lo)
{
    const int z = blockIdx.z;
    const float4* in = (z == 0) ? W0 : (z == 1) ? W1 : W2;
    const int i = blockIdx.x * blockDim.x + threadIdx.x;
    float4 v = in[i];
    uint32_t h0, l0, h1, l1;
    split2h(v.x, v.y, h0, l0);
    split2h(v.z, v.w, h1, l1);
    hi[(size_t)z * 262144 + i] = make_uint2(h0, h1);
    lo[(size_t)z * 262144 + i] = make_uint2(l0, l1);
}
__global__ void __launch_bounds__(256) k_cvt1(const float4* __restrict__ in,
                                              uint2* __restrict__ hi, int n4)
{
    int i = blockIdx.x * blockDim.x + threadIdx.x;
    if (i >= n4) return;
    float4 v = in[i];
    hi[i] = make_uint2(pack2h(v.x, v.y), pack2h(v.z, v.w));
}

// ---- transpose + split: W (1024x1024 fp32) -> W^T hi/lo fp16 planes -------
__global__ void __launch_bounds__(256) k_tr(const float* __restrict__ W0,
                                            const float* __restrict__ W1,
                                            const float* __restrict__ W2)
{
    __shared__ float tile[64][65];
    const int z = blockIdx.z;
    const float* W = (z == 0) ? W0 : (z == 1) ? W1 : W2;
    const int r0 = blockIdx.y * 64, c0 = blockIdx.x * 64;
    const int row = threadIdx.x >> 2, c4 = (threadIdx.x & 3) * 16;

#pragma unroll
    for (int i = 0; i < 4; ++i) {
        float4 v = *(const float4*)(W + (size_t)(r0 + row) * 1024 + c0 + c4 + i * 4);
        tile[row][c4 + i * 4 + 0] = v.x; tile[row][c4 + i * 4 + 1] = v.y;
        tile[row][c4 + i * 4 + 2] = v.z; tile[row][c4 + i * 4 + 3] = v.w;
    }
    __syncthreads();

    uint32_t hb[8], lb[8];
#pragma unroll
    for (int i = 0; i < 8; ++i)
        split2h(tile[c4 + 2 * i][row], tile[c4 + 2 * i + 1][row], hb[i], lb[i]);
    const size_t o = (size_t)z * WSZ + (size_t)(c0 + row) * 1024 + r0 + c4;
    *(uint4*)&g_wth[o]     = make_uint4(hb[0], hb[1], hb[2], hb[3]);
    *(uint4*)&g_wth[o + 8] = make_uint4(hb[4], hb[5], hb[6], hb[7]);
    *(uint4*)&g_wtl[o]     = make_uint4(lb[0], lb[1], lb[2], lb[3]);
    *(uint4*)&g_wtl[o + 8] = make_uint4(lb[4], lb[5], lb[6], lb[7]);
}

// ---- split-fp16 mma.sync GEMM: C = (Ah+Al)*Bh^T [+ Ah*Bl^T if BL] ---------
// 3-buffer cp.async pipeline, single __syncthreads per K-slab.
#define RP    80
#define PLANE 10240

template <int OUT, int BL>
__global__ void __launch_bounds__(256, 2) k_gemm(
    const __half* __restrict__ Ah, const __half* __restrict__ Al,
    int lda, int aoff,
    const __half* __restrict__ Bh, const __half* __restrict__ Bl,
    float* __restrict__ Cf, __half* __restrict__ Ch, __half* __restrict__ Cl,
    int ldc, int coff)
{
    constexpr int BUF = (3 + BL) * PLANE;
    extern __shared__ __align__(16) char sm[];
    const int tid = threadIdx.x;
    const int lane = tid & 31, wid = tid >> 5;
    const int wm = wid & 1, wn = wid >> 1;
    const int z = blockIdx.z;
    const int m0 = blockIdx.y * 128, n0 = blockIdx.x * 128;

    const __half* Azh = Ah + (size_t)z * aoff;
    const __half* Azl = Al + (size_t)z * aoff;
    const __half* Bzh = Bh + (size_t)z * WSZ;
    const __half* Bzl = BL ? (Bl + (size_t)z * WSZ) : nullptr;

    const int row = tid >> 1, half = tid & 1;
    const __half* pAh = Azh + (size_t)(m0 + row) * lda + half * 16;
    const __half* pAl = Azl + (size_t)(m0 + row) * lda + half * 16;
    const __half* pBh = Bzh + (size_t)(n0 + row) * 1024 + half * 16;
    const __half* pBl = BL ? (Bzl + (size_t)(n0 + row) * 1024 + half * 16) : nullptr;
    const uint32_t sb = smem_u32(sm);
    const uint32_t drow = (uint32_t)row * RP + half * 32;

    auto load_slab = [&](int buf, int kt) {
        const uint32_t d = sb + buf * BUF + drow;
        const int ko = kt * 32;
        cpa16(d,                 pAh + ko); cpa16(d + 16,             pAh + ko + 8);
        cpa16(d + PLANE,         pAl + ko); cpa16(d + PLANE + 16,     pAl + ko + 8);
        cpa16(d + 2 * PLANE,     pBh + ko); cpa16(d + 2 * PLANE + 16, pBh + ko + 8);
        if (BL) {
            cpa16(d + 3 * PLANE,      pBl + ko);
            cpa16(d + 3 * PLANE + 16, pBl + ko + 8);
        }
        asm volatile("cp.async.commit_group;" ::: "memory");
    };

    float acc[4][4][4];
#pragma unroll
    for (int i = 0; i < 4; ++i)
#pragma unroll
        for (int j = 0; j < 4; ++j)
#pragma unroll
            for (int r = 0; r < 4; ++r) acc[i][j][r] = 0.f;

    load_slab(0, 0);
    load_slab(1, 1);

    const uint32_t a_base = (uint32_t)(wm * 64 + (lane & 15)) * RP + (lane >> 4) * 16;
    const uint32_t b_base = 2 * PLANE + (uint32_t)(wn * 32 + (lane & 15)) * RP
                            + (lane >> 4) * 16;

    int cur = 0, pre = 2;   // kt%3 and (kt+2)%3
    for (int kt = 0; kt < 32; ++kt) {
        if (kt < 31) asm volatile("cp.async.wait_group 1;" ::: "memory");
        else         asm volatile("cp.async.wait_group 0;" ::: "memory");
        __syncthreads();
        if (kt + 2 < 32) load_slab(pre, kt + 2);   // buf free: readers passed sync
        const uint32_t bufb = sb + cur * BUF;
#pragma unroll
        for (int s = 0; s < 2; ++s) {
            const uint32_t stepb = bufb + s * 32;
            uint32_t ah[4][4], bh[2][4];
#pragma unroll
            for (int mi = 0; mi < 4; ++mi) ldsm4(ah[mi], stepb + a_base + mi * 1280);
#pragma unroll
            for (int p = 0; p < 2; ++p) ldsm4(bh[p], stepb + b_base + p * 1280);
#pragma unroll
            for (int mi = 0; mi < 4; ++mi)
#pragma unroll
                for (int p = 0; p < 2; ++p) {
                    mma_f16(acc[mi][2 * p],     ah[mi], bh[p][0], bh[p][2]);
                    mma_f16(acc[mi][2 * p + 1], ah[mi], bh[p][1], bh[p][3]);
                }
            if (BL) {
                uint32_t bl[2][4];
#pragma unroll
                for (int p = 0; p < 2; ++p)
                    ldsm4(bl[p], stepb + b_base + PLANE + p * 1280);
#pragma unroll
                for (int mi = 0; mi < 4; ++mi)
#pragma unroll
                    for (int p = 0; p < 2; ++p) {
                        mma_f16(acc[mi][2 * p],     ah[mi], bl[p][0], bl[p][2]);
                        mma_f16(acc[mi][2 * p + 1], ah[mi], bl[p][1], bl[p][3]);
                    }
            }
#pragma unroll
            for (int mi = 0; mi < 4; ++mi) ldsm4(ah[mi], stepb + a_base + PLANE + mi * 1280);
#pragma unroll
            for (int mi = 0; mi < 4; ++mi)
#pragma unroll
                for (int p = 0; p < 2; ++p) {
                    mma_f16(acc[mi][2 * p],     ah[mi], bh[p][0], bh[p][2]);
                    mma_f16(acc[mi][2 * p + 1], ah[mi], bh[p][1], bh[p][3]);
                }
        }
        cur = (cur == 2) ? 0 : cur + 1;
        pre = (pre == 2) ? 0 : pre + 1;
    }

    const int t4 = lane >> 2, t2 = lane & 3;
#pragma unroll
    for (int mi = 0; mi < 4; ++mi) {
        const int r0 = m0 + wm * 64 + mi * 16 + t4;
#pragma unroll
        for (int nj = 0; nj < 4; ++nj) {
            const int cc = n0 + wn * 32 + (nj >> 1) * 16 + (nj & 1) * 8 + 2 * t2;
            const float* c = acc[mi][nj];
            const size_t o = (size_t)r0 * ldc + (size_t)z * coff + cc;
            if (OUT == 0) {
                *(float2*)&Cf[o]           = make_float2(c[0], c[1]);
                *(float2*)&Cf[o + 8 * ldc] = make_float2(c[2], c[3]);
            } else {
                uint32_t h, l;
                split2h(c[0], c[1], h, l);
                *(uint32_t*)&Ch[o] = h;           *(uint32_t*)&Cl[o] = l;
                split2h(c[2], c[3], h, l);
                *(uint32_t*)&Ch[o + 8 * ldc] = h; *(uint32_t*)&Cl[o + 8 * ldc] = l;
            }
        }
    }
}

// ---- HMMA flash attention (proven R10 kernel) -----------------------------
#define RPA   144
#define QPL   18432
#define KVSL  55296
#define ADSM  147456

__global__ void __launch_bounds__(256) k_att()
{
    extern __shared__ __align__(16) char sm[];
    const int tid = threadIdx.x;
    const int lane = tid & 31, wid = tid >> 5;
    const int n = blockIdx.y >> 4, h = blockIdx.y & 15;
    const int l0 = blockIdx.x * 128;
    const uint32_t sb = smem_u32(sm);

    const int row = tid >> 1, half = tid & 1;
    const size_t qrow = (size_t)(n * LSEQ + l0 + row) * QKVC + h * 64 + half * 32;
    const uint32_t drow = (uint32_t)row * RPA + half * 64;

    {
        const __half* sh = g_qkvh + qrow;
        const __half* sl = g_qkvl + qrow;
#pragma unroll
        for (int j = 0; j < 4; ++j) {
            cpa16(sb + drow + j * 16,       sh + j * 8);
            cpa16(sb + QPL + drow + j * 16, sl + j * 8);
        }
    }
    const size_t krow0 = (size_t)(n * LSEQ + row) * QKVC + 1024 + h * 64 + half * 32;
    auto load_kv = [&](int buf, int t) {
        const uint32_t d = sb + 2 * QPL + buf * KVSL + drow;
        const size_t src = krow0 + (size_t)t * 128 * QKVC;
#pragma unroll
        for (int j = 0; j < 4; ++j) {
            cpa16(d + j * 16,         g_qkvh + src + j * 8);
            cpa16(d + 18432 + j * 16, g_qkvl + src + j * 8);
            cpa16(d + 36864 + j * 16, g_qkvh + src + 1024 + j * 8);
        }
        asm volatile("cp.async.commit_group;" ::: "memory");
    };
    load_kv(0, 0);
    load_kv(1, 1);

    float o[8][4];
#pragma unroll
    for (int i = 0; i < 8; ++i)
#pragma unroll
        for (int r = 0; r < 4; ++r) o[i][r] = 0.f;
    float m0 = -3.0e38f, m1 = -3.0e38f, l0s = 0.f, l1s = 0.f;

    const int wr = wid * 16;
    const uint32_t a_addr = (uint32_t)(wr + (lane & 15)) * RPA + (lane >> 4) * 16;
    const uint32_t vrow = (uint32_t)(lane & 15) * RPA + ((lane & 16) ? 16 : 0);

    for (int t = 0; t < 16; ++t) {
        if (t < 14) asm volatile("cp.async.wait_group 1;" ::: "memory");
        else        asm volatile("cp.async.wait_group 0;" ::: "memory");
        __syncthreads();
        const uint32_t KH = sb + 2 * QPL + (t & 1) * KVSL;
        const uint32_t KL = KH + 18432, VH = KH + 36864;

        float sc[16][4];
#pragma unroll
        for (int f = 0; f < 16; ++f)
#pragma unroll
            for (int r = 0; r < 4; ++r) sc[f][r] = 0.f;

#pragma unroll
        for (int s = 0; s < 4; ++s) {
            uint32_t aqh[4], aql[4];
            ldsm4(aqh, sb + a_addr + s * 32);
            ldsm4(aql, sb + QPL + a_addr + s * 32);
#pragma unroll
            for (int nb = 0; nb < 8; ++nb) {
                const uint32_t kaddr = (uint32_t)(nb * 16 + (lane & 15)) * RPA
                                       + s * 32 + (lane >> 4) * 16;
                uint32_t bh[4], bl[4];
                ldsm4(bh, KH + kaddr);
                mma_f16(sc[2 * nb],     aqh, bh[0], bh[2]);
                mma_f16(sc[2 * nb + 1], aqh, bh[1], bh[3]);
                mma_f16(sc[2 * nb],     aql, bh[0], bh[2]);
                mma_f16(sc[2 * nb + 1], aql, bh[1], bh[3]);
                ldsm4(bl, KL + kaddr);
                mma_f16(sc[2 * nb],     aqh, bl[0], bl[2]);
                mma_f16(sc[2 * nb + 1], aqh, bl[1], bl[3]);
            }
        }

        float rm0 = -3.0e38f, rm1 = -3.0e38f;
#pragma unroll
        for (int f = 0; f < 16; ++f) {
#pragma unroll
            for (int r = 0; r < 4; ++r) sc[f][r] *= 0.125f;
            rm0 = fmaxf(rm0, fmaxf(sc[f][0], sc[f][1]));
            rm1 = fmaxf(rm1, fmaxf(sc[f][2], sc[f][3]));
        }
#pragma unroll
        for (int off = 1; off <= 2; off <<= 1) {
            rm0 = fmaxf(rm0, __shfl_xor_sync(0xffffffffu, rm0, off));
            rm1 = fmaxf(rm1, __shfl_xor_sync(0xffffffffu, rm1, off));
        }
        const float mn0 = fmaxf(m0, rm0), mn1 = fmaxf(m1, rm1);
        const float al0 = __expf(m0 - mn0), al1 = __expf(m1 - mn1);
        m0 = mn0; m1 = mn1;
        float rs0 = 0.f, rs1 = 0.f;
#pragma unroll
        for (int f = 0; f < 16; ++f) {
            sc[f][0] = __expf(sc[f][0] - mn0); sc[f][1] = __expf(sc[f][1] - mn0);
            sc[f][2] = __expf(sc[f][2] - mn1); sc[f][3] = __expf(sc[f][3] - mn1);
            rs0 += sc[f][0] + sc[f][1];
            rs1 += sc[f][2] + sc[f][3];
        }
#pragma unroll
        for (int off = 1; off <= 2; off <<= 1) {
            rs0 += __shfl_xor_sync(0xffffffffu, rs0, off);
            rs1 += __shfl_xor_sync(0xffffffffu, rs1, off);
        }
        l0s = l0s * al0 + rs0;
        l1s = l1s * al1 + rs1;
#pragma unroll
        for (int i = 0; i < 8; ++i) {
            o[i][0] *= al0; o[i][1] *= al0; o[i][2] *= al1; o[i][3] *= al1;
        }

#pragma unroll
        for (int g = 0; g < 8; ++g) {
            uint32_t ap[4], alp[4];
            split2h(sc[2 * g][0],     sc[2 * g][1],     ap[0], alp[0]);
            split2h(sc[2 * g][2],     sc[2 * g][3],     ap[1], alp[1]);
            split2h(sc[2 * g + 1][0], sc[2 * g + 1][1], ap[2], alp[2]);
            split2h(sc[2 * g + 1][2], sc[2 * g + 1][3], ap[3], alp[3]);
#pragma unroll
            for (int nbp = 0; nbp < 4; ++nbp) {
                uint32_t bv[4];
                ldsm4t(bv, VH + vrow + (uint32_t)g * 16 * RPA + nbp * 32);
                mma_f16(o[2 * nbp],     ap,  bv[0], bv[1]);
                mma_f16(o[2 * nbp + 1], ap,  bv[2], bv[3]);
                mma_f16(o[2 * nbp],     alp, bv[0], bv[1]);
                mma_f16(o[2 * nbp + 1], alp, bv[2], bv[3]);
            }
        }
        __syncthreads();
        if (t + 2 < 16) load_kv(t & 1, t + 2);
    }

    const float inv0 = 1.0f / l0s, inv1 = 1.0f / l1s;
    const int t4 = lane >> 2, t2 = lane & 3;
    const size_t r0 = (size_t)(n * LSEQ + l0 + wr + t4) * EDIM + h * 64 + 2 * t2;
    const size_t r1 = r0 + 8 * EDIM;
#pragma unroll
    for (int nb = 0; nb < 8; ++nb) {
        uint32_t hh, ll;
        split2h(o[nb][0] * inv0, o[nb][1] * inv0, hh, ll);
        *(uint32_t*)&g_atth[r0 + 8 * nb] = hh;
        *(uint32_t*)&g_attl[r0 + 8 * nb] = ll;
        split2h(o[nb][2] * inv1, o[nb][3] * inv1, hh, ll);
        *(uint32_t*)&g_atth[r1 + 8 * nb] = hh;
        *(uint32_t*)&g_attl[r1 + 8 * nb] = ll;
    }
}

extern "C" void kernel_launch(void* const* d_in, const int* in_sizes, int n_in,
                              void* d_out, int out_size)
{
    const float* x    = (const float*)d_in[0];
    const float* Wq   = (const float*)d_in[1];
    const float* Wk   = (const float*)d_in[2];
    const float* Wv   = (const float*)d_in[3];
    const float* Wqp  = (const float*)d_in[4];
    const float* Wkp  = (const float*)d_in[5];
    const float* Wvp  = (const float*)d_in[6];
    const float* Wout = (const float*)d_in[7];
    float* outp = (float*)d_out;

    const int DSM3 = 3 * 3 * PLANE;   // 92160 (3 buffers x 3 planes)
    const int DSM4 = 3 * 4 * PLANE;   // 122880
    cudaFuncSetAttribute((const void*)k_gemm<0, 0>,
                         cudaFuncAttributeMaxDynamicSharedMemorySize, DSM3);
    cudaFuncSetAttribute((const void*)k_gemm<1, 0>,
                         cudaFuncAttributeMaxDynamicSharedMemorySize, DSM3);
    cudaFuncSetAttribute((const void*)k_gemm<1, 1>,
                         cudaFuncAttributeMaxDynamicSharedMemorySize, DSM4);
    cudaFuncSetAttribute((const void*)k_att,
                         cudaFuncAttributeMaxDynamicSharedMemorySize, ADSM);

    __half *xh, *xl, *wph, *wpl, *wth, *wtl, *wch, *wcl, *wouth;
    __half *qkvh, *qkvl, *atth, *attl;
    cudaGetSymbolAddress((void**)&xh, g_xh);     cudaGetSymbolAddress((void**)&xl, g_xl);
    cudaGetSymbolAddress((void**)&wph, g_wph);   cudaGetSymbolAddress((void**)&wpl, g_wpl);
    cudaGetSymbolAddress((void**)&wth, g_wth);   cudaGetSymbolAddress((void**)&wtl, g_wtl);
    cudaGetSymbolAddress((void**)&wch, g_wch);   cudaGetSymbolAddress((void**)&wcl, g_wcl);
    cudaGetSymbolAddress((void**)&wouth, g_wouth);
    cudaGetSymbolAddress((void**)&qkvh, g_qkvh); cudaGetSymbolAddress((void**)&qkvl, g_qkvl);
    cudaGetSymbolAddress((void**)&atth, g_atth); cudaGetSymbolAddress((void**)&attl, g_attl);

    // launches 0-3: conversions (batched so launch #5 = qkv GEMM for ncu -s 5)
    k_cvt2<<<(MTOK * EDIM / 4 + 255) / 256, 256>>>((const float4*)x, (uint2*)xh,
                                                   (uint2*)xl, MTOK * EDIM / 4);
    k_tr<<<dim3(16, 16, 3), 256>>>(Wq, Wk, Wv);
    k_cvt2w<<<dim3(1024, 1, 3), 256>>>((const float4*)Wqp, (const float4*)Wkp,
                                       (const float4*)Wvp, (uint2*)wph, (uint2*)wpl);
    k_cvt1<<<1024, 256>>>((const float4*)Wout, (uint2*)wouth, 262144);

    // 4: combine Wc_z = Wzp @ Wz (3-term)
    k_gemm<1, 1><<<dim3(8, 8, 3), 256, DSM4>>>(wph, wpl, 1024, WSZ, wth, wtl,
                                               nullptr, wch, wcl, 1024, WSZ);
    // 5: qkv = x @ Wc^T (2-term)  <- ncu capture target
    k_gemm<1, 0><<<dim3(8, 64, 3), 256, DSM3>>>(xh, xl, EDIM, 0, wch, nullptr,
                                                nullptr, qkvh, qkvl, QKVC, 1024);
    // 6: attention
    k_att<<<dim3(LSEQ / 128, NB * NH), 256, ADSM>>>();
    // 7: out = att @ Wout^T (fp32)
    k_gemm<0, 0><<<dim3(8, 64, 1), 256, DSM3>>>(atth, attl, EDIM, 0, wouth, nullptr,
                                                outp, nullptr, nullptr, EDIM, 0);
}

// round 14
// speedup vs baseline: 4.0512x; 1.5361x over previous
#include <cuda_runtime.h>
#include <cuda_fp16.h>
#include <cstdint>

#define EDIM 1024
#define LSEQ 2048
#define NB   4
#define NH   16
#define MTOK 8192
#define QKVC 3072
#define WSZ  1048576u

__device__ __half g_xh[(size_t)MTOK * EDIM];
__device__ __half g_wph[3u * WSZ], g_wpl[3u * WSZ];     // Wqp/Wkp/Wvp hi/lo
__device__ __half g_wth[3u * WSZ], g_wtl[3u * WSZ];     // Wq^T/Wk^T/Wv^T hi/lo
__device__ __half g_wch[3u * WSZ];                      // Wc = Wp@W (hi)
__device__ __half g_wouth[WSZ];
__device__ __half g_qkvh[(size_t)MTOK * QKVC];
__device__ __half g_atth[(size_t)MTOK * EDIM];

// ---- helpers --------------------------------------------------------------
__device__ __forceinline__ uint32_t smem_u32(const void* p) {
    uint32_t a;
    asm("{ .reg .u64 t; cvta.to.shared.u64 t, %1; cvt.u32.u64 %0, t; }"
        : "=r"(a) : "l"(p));
    return a;
}
__device__ __forceinline__ void split2h(float a, float b, uint32_t& hi, uint32_t& lo) {
    asm("cvt.rn.f16x2.f32 %0, %1, %2;" : "=r"(hi) : "f"(b), "f"(a));
    __half2 h = *reinterpret_cast<__half2*>(&hi);
    float ar = a - __half2float(__low2half(h));
    float br = b - __half2float(__high2half(h));
    asm("cvt.rn.f16x2.f32 %0, %1, %2;" : "=r"(lo) : "f"(br), "f"(ar));
}
__device__ __forceinline__ uint32_t pack2h(float a, float b) {
    uint32_t r;
    asm("cvt.rn.f16x2.f32 %0, %1, %2;" : "=r"(r) : "f"(b), "f"(a));
    return r;
}
__device__ __forceinline__ void ldsm4(uint32_t* r, uint32_t a) {
    asm volatile("ldmatrix.sync.aligned.m8n8.x4.shared.b16 {%0,%1,%2,%3}, [%4];"
                 : "=r"(r[0]), "=r"(r[1]), "=r"(r[2]), "=r"(r[3]) : "r"(a));
}
__device__ __forceinline__ void ldsm4t(uint32_t* r, uint32_t a) {
    asm volatile("ldmatrix.sync.aligned.m8n8.x4.trans.shared.b16 {%0,%1,%2,%3}, [%4];"
                 : "=r"(r[0]), "=r"(r[1]), "=r"(r[2]), "=r"(r[3]) : "r"(a));
}
__device__ __forceinline__ void mma_f16(float* c, const uint32_t* a,
                                        uint32_t b0, uint32_t b1) {
    asm volatile("mma.sync.aligned.m16n8k16.row.col.f32.f16.f16.f32 "
                 "{%0,%1,%2,%3}, {%4,%5,%6,%7}, {%8,%9}, {%0,%1,%2,%3};"
                 : "+f"(c[0]), "+f"(c[1]), "+f"(c[2]), "+f"(c[3])
                 : "r"(a[0]), "r"(a[1]), "r"(a[2]), "r"(a[3]), "r"(b0), "r"(b1));
}
__device__ __forceinline__ void cpa16(uint32_t d, const void* s) {
    asm volatile("cp.async.cg.shared.global [%0], [%1], 16;" :: "r"(d), "l"(s)
                 : "memory");
}

// ---- converters -----------------------------------------------------------
__global__ void __launch_bounds__(256) k_cvt1(const float4* __restrict__ in,
                                              uint2* __restrict__ hi, int n4)
{
    int i = blockIdx.x * blockDim.x + threadIdx.x;
    if (i >= n4) return;
    float4 v = in[i];
    hi[i] = make_uint2(pack2h(v.x, v.y), pack2h(v.z, v.w));
}
__global__ void __launch_bounds__(256) k_cvt2w(const float4* __restrict__ W0,
                                               const float4* __restrict__ W1,
                                               const float4* __restrict__ W2,
                                               uint2* __restrict__ hi,
                                               uint2* __restrict__ lo)
{
    const int z = blockIdx.z;
    const float4* in = (z == 0) ? W0 : (z == 1) ? W1 : W2;
    const int i = blockIdx.x * blockDim.x + threadIdx.x;
    float4 v = in[i];
    uint32_t h0, l0, h1, l1;
    split2h(v.x, v.y, h0, l0);
    split2h(v.z, v.w, h1, l1);
    hi[(size_t)z * 262144 + i] = make_uint2(h0, h1);
    lo[(size_t)z * 262144 + i] = make_uint2(l0, l1);
}

// ---- transpose + split: W (1024x1024 fp32) -> W^T hi/lo fp16 planes -------
__global__ void __launch_bounds__(256) k_tr(const float* __restrict__ W0,
                                            const float* __restrict__ W1,
                                            const float* __restrict__ W2)
{
    __shared__ float tile[64][65];
    const int z = blockIdx.z;
    const float* W = (z == 0) ? W0 : (z == 1) ? W1 : W2;
    const int r0 = blockIdx.y * 64, c0 = blockIdx.x * 64;
    const int row = threadIdx.x >> 2, c4 = (threadIdx.x & 3) * 16;

#pragma unroll
    for (int i = 0; i < 4; ++i) {
        float4 v = *(const float4*)(W + (size_t)(r0 + row) * 1024 + c0 + c4 + i * 4);
        tile[row][c4 + i * 4 + 0] = v.x; tile[row][c4 + i * 4 + 1] = v.y;
        tile[row][c4 + i * 4 + 2] = v.z; tile[row][c4 + i * 4 + 3] = v.w;
    }
    __syncthreads();

    uint32_t hb[8], lb[8];
#pragma unroll
    for (int i = 0; i < 8; ++i)
        split2h(tile[c4 + 2 * i][row], tile[c4 + 2 * i + 1][row], hb[i], lb[i]);
    const size_t o = (size_t)z * WSZ + (size_t)(c0 + row) * 1024 + r0 + c4;
    *(uint4*)&g_wth[o]     = make_uint4(hb[0], hb[1], hb[2], hb[3]);
    *(uint4*)&g_wth[o + 8] = make_uint4(hb[4], hb[5], hb[6], hb[7]);
    *(uint4*)&g_wtl[o]     = make_uint4(lb[0], lb[1], lb[2], lb[3]);
    *(uint4*)&g_wtl[o + 8] = make_uint4(lb[4], lb[5], lb[6], lb[7]);
}

// ---- split-fp16 mma.sync GEMM ---------------------------------------------
// C = Ah*Bh^T [+ Al*Bh^T if AL] [+ Ah*Bl^T if BL]
// OUT: 0 = fp32 C, 2 = fp16 hi C. 3-buffer cp.async, single sync per slab.
#define RP    80
#define PLANE 10240

template <int OUT, int AL, int BL>
__global__ void __launch_bounds__(256, 2) k_gemm(
    const __half* __restrict__ Ah, const __half* __restrict__ Al,
    int lda, int aoff,
    const __half* __restrict__ Bh, const __half* __restrict__ Bl,
    float* __restrict__ Cf, __half* __restrict__ Ch,
    int ldc, int coff)
{
    constexpr int BUF = (2 + AL + BL) * PLANE;
    constexpr int BOFF = (1 + AL) * PLANE;
    extern __shared__ __align__(16) char sm[];
    const int tid = threadIdx.x;
    const int lane = tid & 31, wid = tid >> 5;
    const int wm = wid & 1, wn = wid >> 1;
    const int z = blockIdx.z;
    const int m0 = blockIdx.y * 128, n0 = blockIdx.x * 128;

    const __half* Azh = Ah + (size_t)z * aoff;
    const __half* Azl = AL ? (Al + (size_t)z * aoff) : nullptr;
    const __half* Bzh = Bh + (size_t)z * WSZ;
    const __half* Bzl = BL ? (Bl + (size_t)z * WSZ) : nullptr;

    const int row = tid >> 1, half = tid & 1;
    const __half* pAh = Azh + (size_t)(m0 + row) * lda + half * 16;
    const __half* pAl = AL ? (Azl + (size_t)(m0 + row) * lda + half * 16) : nullptr;
    const __half* pBh = Bzh + (size_t)(n0 + row) * 1024 + half * 16;
    const __half* pBl = BL ? (Bzl + (size_t)(n0 + row) * 1024 + half * 16) : nullptr;
    const uint32_t sb = smem_u32(sm);
    const uint32_t drow = (uint32_t)row * RP + half * 32;

    auto load_slab = [&](int buf, int kt) {
        const uint32_t d = sb + buf * BUF + drow;
        const int ko = kt * 32;
        cpa16(d,        pAh + ko); cpa16(d + 16,        pAh + ko + 8);
        if (AL) { cpa16(d + PLANE, pAl + ko); cpa16(d + PLANE + 16, pAl + ko + 8); }
        cpa16(d + BOFF, pBh + ko); cpa16(d + BOFF + 16, pBh + ko + 8);
        if (BL) {
            cpa16(d + BOFF + PLANE,      pBl + ko);
            cpa16(d + BOFF + PLANE + 16, pBl + ko + 8);
        }
        asm volatile("cp.async.commit_group;" ::: "memory");
    };

    float acc[4][4][4];
#pragma unroll
    for (int i = 0; i < 4; ++i)
#pragma unroll
        for (int j = 0; j < 4; ++j)
#pragma unroll
            for (int r = 0; r < 4; ++r) acc[i][j][r] = 0.f;

    load_slab(0, 0);
    load_slab(1, 1);

    const uint32_t a_base = (uint32_t)(wm * 64 + (lane & 15)) * RP + (lane >> 4) * 16;
    const uint32_t b_base = BOFF + (uint32_t)(wn * 32 + (lane & 15)) * RP
                            + (lane >> 4) * 16;

    int cur = 0, pre = 2;
    for (int kt = 0; kt < 32; ++kt) {
        if (kt < 31) asm volatile("cp.async.wait_group 1;" ::: "memory");
        else         asm volatile("cp.async.wait_group 0;" ::: "memory");
        __syncthreads();
        if (kt + 2 < 32) load_slab(pre, kt + 2);
        const uint32_t bufb = sb + cur * BUF;
#pragma unroll
        for (int s = 0; s < 2; ++s) {
            const uint32_t stepb = bufb + s * 32;
            uint32_t ah[4][4], bh[2][4];
#pragma unroll
            for (int mi = 0; mi < 4; ++mi) ldsm4(ah[mi], stepb + a_base + mi * 1280);
#pragma unroll
            for (int p = 0; p < 2; ++p) ldsm4(bh[p], stepb + b_base + p * 1280);
#pragma unroll
            for (int mi = 0; mi < 4; ++mi)
#pragma unroll
                for (int p = 0; p < 2; ++p) {
                    mma_f16(acc[mi][2 * p],     ah[mi], bh[p][0], bh[p][2]);
                    mma_f16(acc[mi][2 * p + 1], ah[mi], bh[p][1], bh[p][3]);
                }
            if (BL) {
                uint32_t bl[2][4];
#pragma unroll
                for (int p = 0; p < 2; ++p)
                    ldsm4(bl[p], stepb + b_base + PLANE + p * 1280);
#pragma unroll
                for (int mi = 0; mi < 4; ++mi)
#pragma unroll
                    for (int p = 0; p < 2; ++p) {
                        mma_f16(acc[mi][2 * p],     ah[mi], bl[p][0], bl[p][2]);
                        mma_f16(acc[mi][2 * p + 1], ah[mi], bl[p][1], bl[p][3]);
                    }
            }
            if (AL) {
#pragma unroll
                for (int mi = 0; mi < 4; ++mi)
                    ldsm4(ah[mi], stepb + a_base + PLANE + mi * 1280);
#pragma unroll
                for (int mi = 0; mi < 4; ++mi)
#pragma unroll
                    for (int p = 0; p < 2; ++p) {
                        mma_f16(acc[mi][2 * p],     ah[mi], bh[p][0], bh[p][2]);
                        mma_f16(acc[mi][2 * p + 1], ah[mi], bh[p][1], bh[p][3]);
                    }
            }
        }
        cur = (cur == 2) ? 0 : cur + 1;
        pre = (pre == 2) ? 0 : pre + 1;
    }

    const int t4 = lane >> 2, t2 = lane & 3;
#pragma unroll
    for (int mi = 0; mi < 4; ++mi) {
        const int r0 = m0 + wm * 64 + mi * 16 + t4;
#pragma unroll
        for (int nj = 0; nj < 4; ++nj) {
            const int cc = n0 + wn * 32 + (nj >> 1) * 16 + (nj & 1) * 8 + 2 * t2;
            const float* c = acc[mi][nj];
            const size_t o = (size_t)r0 * ldc + (size_t)z * coff + cc;
            if (OUT == 0) {
                *(float2*)&Cf[o]           = make_float2(c[0], c[1]);
                *(float2*)&Cf[o + 8 * ldc] = make_float2(c[2], c[3]);
            } else {
                *(uint32_t*)&Ch[o]           = pack2h(c[0], c[1]);
                *(uint32_t*)&Ch[o + 8 * ldc] = pack2h(c[2], c[3]);
            }
        }
    }
}

// ---- HMMA flash attention: QK 1-term, PV 2-term ---------------------------
#define RPA   144
#define QPL   18432           /* 128*144: Q hi plane */
#define KVSL  36864           /* Kh | Vh */
#define ADSM  92160           /* QPL + 2*KVSL */

__global__ void __launch_bounds__(256) k_att()
{
    extern __shared__ __align__(16) char sm[];
    const int tid = threadIdx.x;
    const int lane = tid & 31, wid = tid >> 5;
    const int n = blockIdx.y >> 4, h = blockIdx.y & 15;
    const int l0 = blockIdx.x * 128;
    const uint32_t sb = smem_u32(sm);

    const int row = tid >> 1, half = tid & 1;
    const size_t qrow = (size_t)(n * LSEQ + l0 + row) * QKVC + h * 64 + half * 32;
    const uint32_t drow = (uint32_t)row * RPA + half * 64;

    {
        const __half* sh = g_qkvh + qrow;
#pragma unroll
        for (int j = 0; j < 4; ++j)
            cpa16(sb + drow + j * 16, sh + j * 8);
    }
    const size_t krow0 = (size_t)(n * LSEQ + row) * QKVC + 1024 + h * 64 + half * 32;
    auto load_kv = [&](int buf, int t) {
        const uint32_t d = sb + QPL + buf * KVSL + drow;
        const size_t src = krow0 + (size_t)t * 128 * QKVC;
#pragma unroll
        for (int j = 0; j < 4; ++j) {
            cpa16(d + j * 16,         g_qkvh + src + j * 8);           // Kh
            cpa16(d + 18432 + j * 16, g_qkvh + src + 1024 + j * 8);    // Vh
        }
        asm volatile("cp.async.commit_group;" ::: "memory");
    };
    load_kv(0, 0);
    load_kv(1, 1);

    float o[8][4];
#pragma unroll
    for (int i = 0; i < 8; ++i)
#pragma unroll
        for (int r = 0; r < 4; ++r) o[i][r] = 0.f;
    float m0 = -3.0e38f, m1 = -3.0e38f, l0s = 0.f, l1s = 0.f;

    const int wr = wid * 16;
    const uint32_t a_addr = (uint32_t)(wr + (lane & 15)) * RPA + (lane >> 4) * 16;
    const uint32_t vrow = (uint32_t)(lane & 15) * RPA + ((lane & 16) ? 16 : 0);

    for (int t = 0; t < 16; ++t) {
        if (t < 14) asm volatile("cp.async.wait_group 1;" ::: "memory");
        else        asm volatile("cp.async.wait_group 0;" ::: "memory");
        __syncthreads();
        const uint32_t KH = sb + QPL + (t & 1) * KVSL;
        const uint32_t VH = KH + 18432;

        float sc[16][4];
#pragma unroll
        for (int f = 0; f < 16; ++f)
#pragma unroll
            for (int r = 0; r < 4; ++r) sc[f][r] = 0.f;

#pragma unroll
        for (int s = 0; s < 4; ++s) {
            uint32_t aqh[4];
            ldsm4(aqh, sb + a_addr + s * 32);
#pragma unroll
            for (int nb = 0; nb < 8; ++nb) {
                const uint32_t kaddr = (uint32_t)(nb * 16 + (lane & 15)) * RPA
                                       + s * 32 + (lane >> 4) * 16;
                uint32_t bh[4];
                ldsm4(bh, KH + kaddr);
                mma_f16(sc[2 * nb],     aqh, bh[0], bh[2]);
                mma_f16(sc[2 * nb + 1], aqh, bh[1], bh[3]);
            }
        }

        float rm0 = -3.0e38f, rm1 = -3.0e38f;
#pragma unroll
        for (int f = 0; f < 16; ++f) {
#pragma unroll
            for (int r = 0; r < 4; ++r) sc[f][r] *= 0.125f;
            rm0 = fmaxf(rm0, fmaxf(sc[f][0], sc[f][1]));
            rm1 = fmaxf(rm1, fmaxf(sc[f][2], sc[f][3]));
        }
#pragma unroll
        for (int off = 1; off <= 2; off <<= 1) {
            rm0 = fmaxf(rm0, __shfl_xor_sync(0xffffffffu, rm0, off));
            rm1 = fmaxf(rm1, __shfl_xor_sync(0xffffffffu, rm1, off));
        }
        const float mn0 = fmaxf(m0, rm0), mn1 = fmaxf(m1, rm1);
        const float al0 = __expf(m0 - mn0), al1 = __expf(m1 - mn1);
        m0 = mn0; m1 = mn1;
        float rs0 = 0.f, rs1 = 0.f;
#pragma unroll
        for (int f = 0; f < 16; ++f) {
            sc[f][0] = __expf(sc[f][0] - mn0); sc[f][1] = __expf(sc[f][1] - mn0);
            sc[f][2] = __expf(sc[f][2] - mn1); sc[f][3] = __expf(sc[f][3] - mn1);
            rs0 += sc[f][0] + sc[f][1];
            rs1 += sc[f][2] + sc[f][3];
        }
#pragma unroll
        for (int off = 1; off <= 2; off <<= 1) {
            rs0 += __shfl_xor_sync(0xffffffffu, rs0, off);
            rs1 += __shfl_xor_sync(0xffffffffu, rs1, off);
        }
        l0s = l0s * al0 + rs0;
        l1s = l1s * al1 + rs1;
#pragma unroll
        for (int i = 0; i < 8; ++i) {
            o[i][0] *= al0; o[i][1] *= al0; o[i][2] *= al1; o[i][3] *= al1;
        }

#pragma unroll
        for (int g = 0; g < 8; ++g) {
            uint32_t ap[4], alp[4];
            split2h(sc[2 * g][0],     sc[2 * g][1],     ap[0], alp[0]);
            split2h(sc[2 * g][2],     sc[2 * g][3],     ap[1], alp[1]);
            split2h(sc[2 * g + 1][0], sc[2 * g + 1][1], ap[2], alp[2]);
            split2h(sc[2 * g + 1][2], sc[2 * g + 1][3], ap[3], alp[3]);
#pragma unroll
            for (int nbp = 0; nbp < 4; ++nbp) {
                uint32_t bv[4];
                ldsm4t(bv, VH + vrow + (uint32_t)g * 16 * RPA + nbp * 32);
                mma_f16(o[2 * nbp],     ap,  bv[0], bv[1]);
                mma_f16(o[2 * nbp + 1], ap,  bv[2], bv[3]);
                mma_f16(o[2 * nbp],     alp, bv[0], bv[1]);
                mma_f16(o[2 * nbp + 1], alp, bv[2], bv[3]);
            }
        }
        __syncthreads();
        if (t + 2 < 16) load_kv(t & 1, t + 2);
    }

    const float inv0 = 1.0f / l0s, inv1 = 1.0f / l1s;
    const int t4 = lane >> 2, t2 = lane & 3;
    const size_t r0 = (size_t)(n * LSEQ + l0 + wr + t4) * EDIM + h * 64 + 2 * t2;
    const size_t r1 = r0 + 8 * EDIM;
#pragma unroll
    for (int nb = 0; nb < 8; ++nb) {
        *(uint32_t*)&g_atth[r0 + 8 * nb] = pack2h(o[nb][0] * inv0, o[nb][1] * inv0);
        *(uint32_t*)&g_atth[r1 + 8 * nb] = pack2h(o[nb][2] * inv1, o[nb][3] * inv1);
    }
}

extern "C" void kernel_launch(void* const* d_in, const int* in_sizes, int n_in,
                              void* d_out, int out_size)
{
    const float* x    = (const float*)d_in[0];
    const float* Wq   = (const float*)d_in[1];
    const float* Wk   = (const float*)d_in[2];
    const float* Wv   = (const float*)d_in[3];
    const float* Wqp  = (const float*)d_in[4];
    const float* Wkp  = (const float*)d_in[5];
    const float* Wvp  = (const float*)d_in[6];
    const float* Wout = (const float*)d_in[7];
    float* outp = (float*)d_out;

    const int DSM2 = 3 * 2 * PLANE;   // 61440 (AL=0,BL=0)
    const int DSM4 = 3 * 4 * PLANE;   // 122880 (AL=1,BL=1)
    cudaFuncSetAttribute((const void*)k_gemm<0, 0, 0>,
                         cudaFuncAttributeMaxDynamicSharedMemorySize, DSM2);
    cudaFuncSetAttribute((const void*)k_gemm<2, 0, 0>,
                         cudaFuncAttributeMaxDynamicSharedMemorySize, DSM2);
    cudaFuncSetAttribute((const void*)k_gemm<2, 1, 1>,
                         cudaFuncAttributeMaxDynamicSharedMemorySize, DSM4);
    cudaFuncSetAttribute((const void*)k_att,
                         cudaFuncAttributeMaxDynamicSharedMemorySize, ADSM);

    __half *xh, *wph, *wpl, *wth, *wtl, *wch, *wouth, *qkvh, *atth;
    cudaGetSymbolAddress((void**)&xh, g_xh);
    cudaGetSymbolAddress((void**)&wph, g_wph);   cudaGetSymbolAddress((void**)&wpl, g_wpl);
    cudaGetSymbolAddress((void**)&wth, g_wth);   cudaGetSymbolAddress((void**)&wtl, g_wtl);
    cudaGetSymbolAddress((void**)&wch, g_wch);
    cudaGetSymbolAddress((void**)&wouth, g_wouth);
    cudaGetSymbolAddress((void**)&qkvh, g_qkvh);
    cudaGetSymbolAddress((void**)&atth, g_atth);

    // 0-3: conversions
    k_cvt1<<<(MTOK * EDIM / 4 + 255) / 256, 256>>>((const float4*)x, (uint2*)xh,
                                                   MTOK * EDIM / 4);
    k_tr<<<dim3(16, 16, 3), 256>>>(Wq, Wk, Wv);
    k_cvt2w<<<dim3(1024, 1, 3), 256>>>((const float4*)Wqp, (const float4*)Wkp,
                                       (const float4*)Wvp, (uint2*)wph, (uint2*)wpl);
    k_cvt1<<<1024, 256>>>((const float4*)Wout, (uint2*)wouth, 262144);

    // 4: combine Wc_z = Wzp @ Wz (3-term, fp16 hi out)
    k_gemm<2, 1, 1><<<dim3(8, 8, 3), 256, DSM4>>>(wph, wpl, 1024, WSZ, wth, wtl,
                                                  nullptr, wch, 1024, WSZ);
    // 5: qkv = x @ Wc^T (1-term, fp16 hi out)
    k_gemm<2, 0, 0><<<dim3(8, 64, 3), 256, DSM2>>>(xh, nullptr, EDIM, 0, wch, nullptr,
                                                   nullptr, qkvh, QKVC, 1024);
    // 6: attention (QK 1-term, PV 2-term)
    k_att<<<dim3(LSEQ / 128, NB * NH), 256, ADSM>>>();
    // 7: out = att @ Wout^T (1-term, fp32 out)
    k_gemm<0, 0, 0><<<dim3(8, 64, 1), 256, DSM2>>>(atth, nullptr, EDIM, 0, wouth,
                                                   nullptr, outp, nullptr, EDIM, 0);
}

// round 16
// speedup vs baseline: 4.6306x; 1.1430x over previous
#include <cuda_runtime.h>
#include <cuda_fp16.h>
#include <cstdint>

#define EDIM 1024
#define LSEQ 2048
#define NB   4
#define NH   16
#define MTOK 8192
#define QKVC 3072
#define WSZ  1048576u

__device__ __half g_xh[(size_t)MTOK * EDIM];
__device__ __half g_wph[3u * WSZ], g_wpl[3u * WSZ];     // Wqp/Wkp/Wvp hi/lo
__device__ __half g_wth[3u * WSZ], g_wtl[3u * WSZ];     // Wq^T/Wk^T/Wv^T hi/lo
__device__ __half g_wch[3u * WSZ];                      // Wc = Wp@W (hi; q pre-scaled)
__device__ __half g_wouth[WSZ];
__device__ __half g_qkvh[(size_t)MTOK * QKVC];
__device__ __half g_atth[(size_t)MTOK * EDIM];

// ---- helpers --------------------------------------------------------------
__device__ __forceinline__ uint32_t smem_u32(const void* p) {
    uint32_t a;
    asm("{ .reg .u64 t; cvta.to.shared.u64 t, %1; cvt.u32.u64 %0, t; }"
        : "=r"(a) : "l"(p));
    return a;
}
__device__ __forceinline__ void split2h(float a, float b, uint32_t& hi, uint32_t& lo) {
    asm("cvt.rn.f16x2.f32 %0, %1, %2;" : "=r"(hi) : "f"(b), "f"(a));
    __half2 h = *reinterpret_cast<__half2*>(&hi);
    float ar = a - __half2float(__low2half(h));
    float br = b - __half2float(__high2half(h));
    asm("cvt.rn.f16x2.f32 %0, %1, %2;" : "=r"(lo) : "f"(br), "f"(ar));
}
__device__ __forceinline__ uint32_t pack2h(float a, float b) {
    uint32_t r;
    asm("cvt.rn.f16x2.f32 %0, %1, %2;" : "=r"(r) : "f"(b), "f"(a));
    return r;
}
__device__ __forceinline__ float ex2(float x) {
    float y;
    asm("ex2.approx.ftz.f32 %0, %1;" : "=f"(y) : "f"(x));
    return y;
}
__device__ __forceinline__ void ldsm4(uint32_t* r, uint32_t a) {
    asm volatile("ldmatrix.sync.aligned.m8n8.x4.shared.b16 {%0,%1,%2,%3}, [%4];"
                 : "=r"(r[0]), "=r"(r[1]), "=r"(r[2]), "=r"(r[3]) : "r"(a));
}
__device__ __forceinline__ void ldsm4t(uint32_t* r, uint32_t a) {
    asm volatile("ldmatrix.sync.aligned.m8n8.x4.trans.shared.b16 {%0,%1,%2,%3}, [%4];"
                 : "=r"(r[0]), "=r"(r[1]), "=r"(r[2]), "=r"(r[3]) : "r"(a));
}
__device__ __forceinline__ void mma_f16(float* c, const uint32_t* a,
                                        uint32_t b0, uint32_t b1) {
    asm volatile("mma.sync.aligned.m16n8k16.row.col.f32.f16.f16.f32 "
                 "{%0,%1,%2,%3}, {%4,%5,%6,%7}, {%8,%9}, {%0,%1,%2,%3};"
                 : "+f"(c[0]), "+f"(c[1]), "+f"(c[2]), "+f"(c[3])
                 : "r"(a[0]), "r"(a[1]), "r"(a[2]), "r"(a[3]), "r"(b0), "r"(b1));
}
__device__ __forceinline__ void cpa16(uint32_t d, const void* s) {
    asm volatile("cp.async.cg.shared.global [%0], [%1], 16;" :: "r"(d), "l"(s)
                 : "memory");
}

// ---- converters -----------------------------------------------------------
__global__ void __launch_bounds__(256) k_cvt1(const float4* __restrict__ in,
                                              uint2* __restrict__ hi, int n4)
{
    int i = blockIdx.x * blockDim.x + threadIdx.x;
    if (i >= n4) return;
    float4 v = in[i];
    hi[i] = make_uint2(pack2h(v.x, v.y), pack2h(v.z, v.w));
}
__global__ void __launch_bounds__(256) k_cvt2w(const float4* __restrict__ W0,
                                               const float4* __restrict__ W1,
                                               const float4* __restrict__ W2,
                                               uint2* __restrict__ hi,
                                               uint2* __restrict__ lo)
{
    const int z = blockIdx.z;
    const float4* in = (z == 0) ? W0 : (z == 1) ? W1 : W2;
    const int i = blockIdx.x * blockDim.x + threadIdx.x;
    float4 v = in[i];
    uint32_t h0, l0, h1, l1;
    split2h(v.x, v.y, h0, l0);
    split2h(v.z, v.w, h1, l1);
    hi[(size_t)z * 262144 + i] = make_uint2(h0, h1);
    lo[(size_t)z * 262144 + i] = make_uint2(l0, l1);
}

// ---- transpose + split: W (1024x1024 fp32) -> W^T hi/lo fp16 planes -------
__global__ void __launch_bounds__(256) k_tr(const float* __restrict__ W0,
                                            const float* __restrict__ W1,
                                            const float* __restrict__ W2)
{
    __shared__ float tile[64][65];
    const int z = blockIdx.z;
    const float* W = (z == 0) ? W0 : (z == 1) ? W1 : W2;
    const int r0 = blockIdx.y * 64, c0 = blockIdx.x * 64;
    const int row = threadIdx.x >> 2, c4 = (threadIdx.x & 3) * 16;

#pragma unroll
    for (int i = 0; i < 4; ++i) {
        float4 v = *(const float4*)(W + (size_t)(r0 + row) * 1024 + c0 + c4 + i * 4);
        tile[row][c4 + i * 4 + 0] = v.x; tile[row][c4 + i * 4 + 1] = v.y;
        tile[row][c4 + i * 4 + 2] = v.z; tile[row][c4 + i * 4 + 3] = v.w;
    }
    __syncthreads();

    uint32_t hb[8], lb[8];
#pragma unroll
    for (int i = 0; i < 8; ++i)
        split2h(tile[c4 + 2 * i][row], tile[c4 + 2 * i + 1][row], hb[i], lb[i]);
    const size_t o = (size_t)z * WSZ + (size_t)(c0 + row) * 1024 + r0 + c4;
    *(uint4*)&g_wth[o]     = make_uint4(hb[0], hb[1], hb[2], hb[3]);
    *(uint4*)&g_wth[o + 8] = make_uint4(hb[4], hb[5], hb[6], hb[7]);
    *(uint4*)&g_wtl[o]     = make_uint4(lb[0], lb[1], lb[2], lb[3]);
    *(uint4*)&g_wtl[o + 8] = make_uint4(lb[4], lb[5], lb[6], lb[7]);
}

// ---- split-fp16 mma.sync GEMM ---------------------------------------------
// C = Ah*Bh^T [+ Al*Bh^T if AL] [+ Ah*Bl^T if BL]
// OUT: 0 = fp32 C, 2 = fp16 hi C (scaled by s0 for z==0).
#define RP    80
#define PLANE 10240

template <int OUT, int AL, int BL>
__global__ void __launch_bounds__(256, 2) k_gemm(
    const __half* __restrict__ Ah, const __half* __restrict__ Al,
    int lda, int aoff,
    const __half* __restrict__ Bh, const __half* __restrict__ Bl,
    float* __restrict__ Cf, __half* __restrict__ Ch,
    int ldc, int coff, float s0)
{
    constexpr int BUF = (2 + AL + BL) * PLANE;
    constexpr int BOFF = (1 + AL) * PLANE;
    extern __shared__ __align__(16) char sm[];
    const int tid = threadIdx.x;
    const int lane = tid & 31, wid = tid >> 5;
    const int wm = wid & 1, wn = wid >> 1;
    const int z = blockIdx.z;
    const int m0 = blockIdx.y * 128, n0 = blockIdx.x * 128;
    const float cs = (z == 0) ? s0 : 1.f;

    const __half* Azh = Ah + (size_t)z * aoff;
    const __half* Azl = AL ? (Al + (size_t)z * aoff) : nullptr;
    const __half* Bzh = Bh + (size_t)z * WSZ;
    const __half* Bzl = BL ? (Bl + (size_t)z * WSZ) : nullptr;

    const int row = tid >> 1, half = tid & 1;
    const __half* pAh = Azh + (size_t)(m0 + row) * lda + half * 16;
    const __half* pAl = AL ? (Azl + (size_t)(m0 + row) * lda + half * 16) : nullptr;
    const __half* pBh = Bzh + (size_t)(n0 + row) * 1024 + half * 16;
    const __half* pBl = BL ? (Bzl + (size_t)(n0 + row) * 1024 + half * 16) : nullptr;
    const uint32_t sb = smem_u32(sm);
    const uint32_t drow = (uint32_t)row * RP + half * 32;

    auto load_slab = [&](int buf, int kt) {
        const uint32_t d = sb + buf * BUF + drow;
        const int ko = kt * 32;
        cpa16(d,        pAh + ko); cpa16(d + 16,        pAh + ko + 8);
        if (AL) { cpa16(d + PLANE, pAl + ko); cpa16(d + PLANE + 16, pAl + ko + 8); }
        cpa16(d + BOFF, pBh + ko); cpa16(d + BOFF + 16, pBh + ko + 8);
        if (BL) {
            cpa16(d + BOFF + PLANE,      pBl + ko);
            cpa16(d + BOFF + PLANE + 16, pBl + ko + 8);
        }
        asm volatile("cp.async.commit_group;" ::: "memory");
    };

    float acc[4][4][4];
#pragma unroll
    for (int i = 0; i < 4; ++i)
#pragma unroll
        for (int j = 0; j < 4; ++j)
#pragma unroll
            for (int r = 0; r < 4; ++r) acc[i][j][r] = 0.f;

    load_slab(0, 0);
    load_slab(1, 1);

    const uint32_t a_base = (uint32_t)(wm * 64 + (lane & 15)) * RP + (lane >> 4) * 16;
    const uint32_t b_base = BOFF + (uint32_t)(wn * 32 + (lane & 15)) * RP
                            + (lane >> 4) * 16;

    int cur = 0, pre = 2;
    for (int kt = 0; kt < 32; ++kt) {
        if (kt < 31) asm volatile("cp.async.wait_group 1;" ::: "memory");
        else         asm volatile("cp.async.wait_group 0;" ::: "memory");
        __syncthreads();
        if (kt + 2 < 32) load_slab(pre, kt + 2);
        const uint32_t bufb = sb + cur * BUF;
#pragma unroll
        for (int s = 0; s < 2; ++s) {
            const uint32_t stepb = bufb + s * 32;
            uint32_t ah[4][4], bh[2][4];
#pragma unroll
            for (int mi = 0; mi < 4; ++mi) ldsm4(ah[mi], stepb + a_base + mi * 1280);
#pragma unroll
            for (int p = 0; p < 2; ++p) ldsm4(bh[p], stepb + b_base + p * 1280);
#pragma unroll
            for (int mi = 0; mi < 4; ++mi)
#pragma unroll
                for (int p = 0; p < 2; ++p) {
                    mma_f16(acc[mi][2 * p],     ah[mi], bh[p][0], bh[p][2]);
                    mma_f16(acc[mi][2 * p + 1], ah[mi], bh[p][1], bh[p][3]);
                }
            if (BL) {
                uint32_t bl[2][4];
#pragma unroll
                for (int p = 0; p < 2; ++p)
                    ldsm4(bl[p], stepb + b_base + PLANE + p * 1280);
#pragma unroll
                for (int mi = 0; mi < 4; ++mi)
#pragma unroll
                    for (int p = 0; p < 2; ++p) {
                        mma_f16(acc[mi][2 * p],     ah[mi], bl[p][0], bl[p][2]);
                        mma_f16(acc[mi][2 * p + 1], ah[mi], bl[p][1], bl[p][3]);
                    }
            }
            if (AL) {
#pragma unroll
                for (int mi = 0; mi < 4; ++mi)
                    ldsm4(ah[mi], stepb + a_base + PLANE + mi * 1280);
#pragma unroll
                for (int mi = 0; mi < 4; ++mi)
#pragma unroll
                    for (int p = 0; p < 2; ++p) {
                        mma_f16(acc[mi][2 * p],     ah[mi], bh[p][0], bh[p][2]);
                        mma_f16(acc[mi][2 * p + 1], ah[mi], bh[p][1], bh[p][3]);
                    }
            }
        }
        cur = (cur == 2) ? 0 : cur + 1;
        pre = (pre == 2) ? 0 : pre + 1;
    }

    const int t4 = lane >> 2, t2 = lane & 3;
#pragma unroll
    for (int mi = 0; mi < 4; ++mi) {
        const int r0 = m0 + wm * 64 + mi * 16 + t4;
#pragma unroll
        for (int nj = 0; nj < 4; ++nj) {
            const int cc = n0 + wn * 32 + (nj >> 1) * 16 + (nj & 1) * 8 + 2 * t2;
            const float* c = acc[mi][nj];
            const size_t o = (size_t)r0 * ldc + (size_t)z * coff + cc;
            if (OUT == 0) {
                *(float2*)&Cf[o]           = make_float2(c[0], c[1]);
                *(float2*)&Cf[o + 8 * ldc] = make_float2(c[2], c[3]);
            } else {
                *(uint32_t*)&Ch[o]           = pack2h(c[0] * cs, c[1] * cs);
                *(uint32_t*)&Ch[o + 8 * ldc] = pack2h(c[2] * cs, c[3] * cs);
            }
        }
    }
}

// ---- HMMA flash attention: QK 1-term, PV 1-term, exp2-domain softmax ------
// Q was pre-scaled by 0.125*log2(e) via Wc_q, so S is in exp2 domain.
#define RPA   144
#define QPL   18432           /* 128*144: Q hi plane */
#define KVSL  36864           /* Kh | Vh */
#define ADSM  92160           /* QPL + 2*KVSL */

__global__ void __launch_bounds__(256) k_att()
{
    extern __shared__ __align__(16) char sm[];
    const int tid = threadIdx.x;
    const int lane = tid & 31, wid = tid >> 5;
    const int n = blockIdx.y >> 4, h = blockIdx.y & 15;
    const int l0 = blockIdx.x * 128;
    const uint32_t sb = smem_u32(sm);

    const int row = tid >> 1, half = tid & 1;
    const size_t qrow = (size_t)(n * LSEQ + l0 + row) * QKVC + h * 64 + half * 32;
    const uint32_t drow = (uint32_t)row * RPA + half * 64;

    {
        const __half* sh = g_qkvh + qrow;
#pragma unroll
        for (int j = 0; j < 4; ++j)
            cpa16(sb + drow + j * 16, sh + j * 8);
    }
    const size_t krow0 = (size_t)(n * LSEQ + row) * QKVC + 1024 + h * 64 + half * 32;
    auto load_kv = [&](int buf, int t) {
        const uint32_t d = sb + QPL + buf * KVSL + drow;
        const size_t src = krow0 + (size_t)t * 128 * QKVC;
#pragma unroll
        for (int j = 0; j < 4; ++j) {
            cpa16(d + j * 16,         g_qkvh + src + j * 8);           // Kh
            cpa16(d + 18432 + j * 16, g_qkvh + src + 1024 + j * 8);    // Vh
        }
        asm volatile("cp.async.commit_group;" ::: "memory");
    };
    load_kv(0, 0);
    load_kv(1, 1);

    float o[8][4];
#pragma unroll
    for (int i = 0; i < 8; ++i)
#pragma unroll
        for (int r = 0; r < 4; ++r) o[i][r] = 0.f;
    float m0 = -3.0e38f, m1 = -3.0e38f, l0s = 0.f, l1s = 0.f;

    const int wr = wid * 16;
    const uint32_t a_addr = (uint32_t)(wr + (lane & 15)) * RPA + (lane >> 4) * 16;
    const uint32_t vrow = (uint32_t)(lane & 15) * RPA + ((lane & 16) ? 16 : 0);

    for (int t = 0; t < 16; ++t) {
        if (t < 14) asm volatile("cp.async.wait_group 1;" ::: "memory");
        else        asm volatile("cp.async.wait_group 0;" ::: "memory");
        __syncthreads();
        const uint32_t KH = sb + QPL + (t & 1) * KVSL;
        const uint32_t VH = KH + 18432;

        float sc[16][4];
#pragma unroll
        for (int f = 0; f < 16; ++f)
#pragma unroll
            for (int r = 0; r < 4; ++r) sc[f][r] = 0.f;

#pragma unroll
        for (int s = 0; s < 4; ++s) {
            uint32_t aqh[4];
            ldsm4(aqh, sb + a_addr + s * 32);
#pragma unroll
            for (int nb = 0; nb < 8; ++nb) {
                const uint32_t kaddr = (uint32_t)(nb * 16 + (lane & 15)) * RPA
                                       + s * 32 + (lane >> 4) * 16;
                uint32_t bh[4];
                ldsm4(bh, KH + kaddr);
                mma_f16(sc[2 * nb],     aqh, bh[0], bh[2]);
                mma_f16(sc[2 * nb + 1], aqh, bh[1], bh[3]);
            }
        }

        // online softmax in exp2 domain (rows r0 = c0/c1, r1 = c2/c3)
        float rm0 = -3.0e38f, rm1 = -3.0e38f;
#pragma unroll
        for (int f = 0; f < 16; ++f) {
            rm0 = fmaxf(rm0, fmaxf(sc[f][0], sc[f][1]));
            rm1 = fmaxf(rm1, fmaxf(sc[f][2], sc[f][3]));
        }
#pragma unroll
        for (int off = 1; off <= 2; off <<= 1) {
            rm0 = fmaxf(rm0, __shfl_xor_sync(0xffffffffu, rm0, off));
            rm1 = fmaxf(rm1, __shfl_xor_sync(0xffffffffu, rm1, off));
        }
        const float mn0 = fmaxf(m0, rm0), mn1 = fmaxf(m1, rm1);
        const float al0 = ex2(m0 - mn0), al1 = ex2(m1 - mn1);
        m0 = mn0; m1 = mn1;
        float rs0 = 0.f, rs1 = 0.f;
#pragma unroll
        for (int f = 0; f < 16; ++f) {
            sc[f][0] = ex2(sc[f][0] - mn0); sc[f][1] = ex2(sc[f][1] - mn0);
            sc[f][2] = ex2(sc[f][2] - mn1); sc[f][3] = ex2(sc[f][3] - mn1);
            rs0 += sc[f][0] + sc[f][1];
            rs1 += sc[f][2] + sc[f][3];
        }
#pragma unroll
        for (int off = 1; off <= 2; off <<= 1) {
            rs0 += __shfl_xor_sync(0xffffffffu, rs0, off);
            rs1 += __shfl_xor_sync(0xffffffffu, rs1, off);
        }
        l0s = l0s * al0 + rs0;
        l1s = l1s * al1 + rs1;
#pragma unroll
        for (int i = 0; i < 8; ++i) {
            o[i][0] *= al0; o[i][1] *= al0; o[i][2] *= al1; o[i][3] *= al1;
        }

        // PV 1-term: P packed to fp16 in registers
#pragma unroll
        for (int g = 0; g < 8; ++g) {
            uint32_t ap[4];
            ap[0] = pack2h(sc[2 * g][0],     sc[2 * g][1]);
            ap[1] = pack2h(sc[2 * g][2],     sc[2 * g][3]);
            ap[2] = pack2h(sc[2 * g + 1][0], sc[2 * g + 1][1]);
            ap[3] = pack2h(sc[2 * g + 1][2], sc[2 * g + 1][3]);
#pragma unroll
            for (int nbp = 0; nbp < 4; ++nbp) {
                uint32_t bv[4];
                ldsm4t(bv, VH + vrow + (uint32_t)g * 16 * RPA + nbp * 32);
                mma_f16(o[2 * nbp],     ap, bv[0], bv[1]);
                mma_f16(o[2 * nbp + 1], ap, bv[2], bv[3]);
            }
        }
        __syncthreads();
        if (t + 2 < 16) load_kv(t & 1, t + 2);
    }

    const float inv0 = 1.0f / l0s, inv1 = 1.0f / l1s;
    const int t4 = lane >> 2, t2 = lane & 3;
    const size_t r0 = (size_t)(n * LSEQ + l0 + wr + t4) * EDIM + h * 64 + 2 * t2;
    const size_t r1 = r0 + 8 * EDIM;
#pragma unroll
    for (int nb = 0; nb < 8; ++nb) {
        *(uint32_t*)&g_atth[r0 + 8 * nb] = pack2h(o[nb][0] * inv0, o[nb][1] * inv0);
        *(uint32_t*)&g_atth[r1 + 8 * nb] = pack2h(o[nb][2] * inv1, o[nb][3] * inv1);
    }
}

extern "C" void kernel_launch(void* const* d_in, const int* in_sizes, int n_in,
                              void* d_out, int out_size)
{
    const float* x    = (const float*)d_in[0];
    const float* Wq   = (const float*)d_in[1];
    const float* Wk   = (const float*)d_in[2];
    const float* Wv   = (const float*)d_in[3];
    const float* Wqp  = (const float*)d_in[4];
    const float* Wkp  = (const float*)d_in[5];
    const float* Wvp  = (const float*)d_in[6];
    const float* Wout = (const float*)d_in[7];
    float* outp = (float*)d_out;

    const int DSM2 = 3 * 2 * PLANE;   // 61440
    const int DSM4 = 3 * 4 * PLANE;   // 122880
    cudaFuncSetAttribute((const void*)k_gemm<0, 0, 0>,
                         cudaFuncAttributeMaxDynamicSharedMemorySize, DSM2);
    cudaFuncSetAttribute((const void*)k_gemm<2, 0, 0>,
                         cudaFuncAttributeMaxDynamicSharedMemorySize, DSM2);
    cudaFuncSetAttribute((const void*)k_gemm<2, 1, 1>,
                         cudaFuncAttributeMaxDynamicSharedMemorySize, DSM4);
    cudaFuncSetAttribute((const void*)k_att,
                         cudaFuncAttributeMaxDynamicSharedMemorySize, ADSM);

    __half *xh, *wph, *wpl, *wth, *wtl, *wch, *wouth, *qkvh, *atth;
    cudaGetSymbolAddress((void**)&xh, g_xh);
    cudaGetSymbolAddress((void**)&wph, g_wph);   cudaGetSymbolAddress((void**)&wpl, g_wpl);
    cudaGetSymbolAddress((void**)&wth, g_wth);   cudaGetSymbolAddress((void**)&wtl, g_wtl);
    cudaGetSymbolAddress((void**)&wch, g_wch);
    cudaGetSymbolAddress((void**)&wouth, g_wouth);
    cudaGetSymbolAddress((void**)&qkvh, g_qkvh);
    cudaGetSymbolAddress((void**)&atth, g_atth);

    // 0-3: conversions
    k_cvt1<<<(MTOK * EDIM / 4 + 255) / 256, 256>>>((const float4*)x, (uint2*)xh,
                                                   MTOK * EDIM / 4);
    k_tr<<<dim3(16, 16, 3), 256>>>(Wq, Wk, Wv);
    k_cvt2w<<<dim3(1024, 1, 3), 256>>>((const float4*)Wqp, (const float4*)Wkp,
                                       (const float4*)Wvp, (uint2*)wph, (uint2*)wpl);
    k_cvt1<<<1024, 256>>>((const float4*)Wout, (uint2*)wouth, 262144);

    // 4: combine Wc_z = Wzp @ Wz (3-term; q block pre-scaled by 0.125*log2e)
    k_gemm<2, 1, 1><<<dim3(8, 8, 3), 256, DSM4>>>(wph, wpl, 1024, WSZ, wth, wtl,
                                                  nullptr, wch, 1024, WSZ,
                                                  0.125f * 1.4426950408889634f);
    // 5: qkv = x @ Wc^T (1-term, fp16 hi out)
    k_gemm<2, 0, 0><<<dim3(8, 64, 3), 256, DSM2>>>(xh, nullptr, EDIM, 0, wch, nullptr,
                                                   nullptr, qkvh, QKVC, 1024, 1.f);
    // 6: attention (QK 1-term, PV 1-term, exp2 softmax)
    k_att<<<dim3(LSEQ / 128, NB * NH), 256, ADSM>>>();
    // 7: out = att @ Wout^T (1-term, fp32 out)
    k_gemm<0, 0, 0><<<dim3(8, 64, 1), 256, DSM2>>>(atth, nullptr, EDIM, 0, wouth,
                                                   nullptr, outp, nullptr, EDIM, 0, 1.f);
}

// round 17
// speedup vs baseline: 5.1697x; 1.1164x over previous
#include <cuda_runtime.h>
#include <cuda_fp16.h>
#include <cstdint>

#define EDIM 1024
#define LSEQ 2048
#define NB   4
#define NH   16
#define MTOK 8192
#define QKVC 3072
#define WSZ  1048576u

__device__ __half g_xh[(size_t)MTOK * EDIM];
__device__ __half g_wph[3u * WSZ];                      // Wqp/Wkp/Wvp hi
__device__ __half g_wth[3u * WSZ];                      // Wq^T/Wk^T/Wv^T hi
__device__ __half g_wch[3u * WSZ];                      // Wc = Wp@W (hi; q pre-scaled)
__device__ __half g_wouth[WSZ];
__device__ __half g_qkvh[(size_t)MTOK * QKVC];
__device__ __half g_atth[(size_t)MTOK * EDIM];

// ---- helpers --------------------------------------------------------------
__device__ __forceinline__ uint32_t smem_u32(const void* p) {
    uint32_t a;
    asm("{ .reg .u64 t; cvta.to.shared.u64 t, %1; cvt.u32.u64 %0, t; }"
        : "=r"(a) : "l"(p));
    return a;
}
__device__ __forceinline__ uint32_t pack2h(float a, float b) {
    uint32_t r;
    asm("cvt.rn.f16x2.f32 %0, %1, %2;" : "=r"(r) : "f"(b), "f"(a));
    return r;
}
__device__ __forceinline__ float ex2(float x) {
    float y;
    asm("ex2.approx.ftz.f32 %0, %1;" : "=f"(y) : "f"(x));
    return y;
}
__device__ __forceinline__ void ldsm4(uint32_t* r, uint32_t a) {
    asm volatile("ldmatrix.sync.aligned.m8n8.x4.shared.b16 {%0,%1,%2,%3}, [%4];"
                 : "=r"(r[0]), "=r"(r[1]), "=r"(r[2]), "=r"(r[3]) : "r"(a));
}
__device__ __forceinline__ void ldsm4t(uint32_t* r, uint32_t a) {
    asm volatile("ldmatrix.sync.aligned.m8n8.x4.trans.shared.b16 {%0,%1,%2,%3}, [%4];"
                 : "=r"(r[0]), "=r"(r[1]), "=r"(r[2]), "=r"(r[3]) : "r"(a));
}
__device__ __forceinline__ void mma_f16(float* c, const uint32_t* a,
                                        uint32_t b0, uint32_t b1) {
    asm volatile("mma.sync.aligned.m16n8k16.row.col.f32.f16.f16.f32 "
                 "{%0,%1,%2,%3}, {%4,%5,%6,%7}, {%8,%9}, {%0,%1,%2,%3};"
                 : "+f"(c[0]), "+f"(c[1]), "+f"(c[2]), "+f"(c[3])
                 : "r"(a[0]), "r"(a[1]), "r"(a[2]), "r"(a[3]), "r"(b0), "r"(b1));
}
__device__ __forceinline__ void cpa16(uint32_t d, const void* s) {
    asm volatile("cp.async.cg.shared.global [%0], [%1], 16;" :: "r"(d), "l"(s)
                 : "memory");
}

// ---- converters (4 independent float4 per thread -> MLP ~4) ---------------
__global__ void __launch_bounds__(256) k_cvtx(const float4* __restrict__ in,
                                              uint2* __restrict__ hi)
{
    const int base = blockIdx.x * 1024 + threadIdx.x;
    float4 v0 = in[base], v1 = in[base + 256], v2 = in[base + 512],
           v3 = in[base + 768];
    hi[base]       = make_uint2(pack2h(v0.x, v0.y), pack2h(v0.z, v0.w));
    hi[base + 256] = make_uint2(pack2h(v1.x, v1.y), pack2h(v1.z, v1.w));
    hi[base + 512] = make_uint2(pack2h(v2.x, v2.y), pack2h(v2.z, v2.w));
    hi[base + 768] = make_uint2(pack2h(v3.x, v3.y), pack2h(v3.z, v3.w));
}
// 4 weight matrices: z 0-2 -> wph planes, z 3 -> wouth
__global__ void __launch_bounds__(256) k_cvtw(const float4* __restrict__ W0,
                                              const float4* __restrict__ W1,
                                              const float4* __restrict__ W2,
                                              const float4* __restrict__ W3,
                                              uint2* __restrict__ wph,
                                              uint2* __restrict__ wout)
{
    const int z = blockIdx.z;
    const float4* in = (z == 0) ? W0 : (z == 1) ? W1 : (z == 2) ? W2 : W3;
    uint2* out = (z < 3) ? (wph + (size_t)z * 262144) : wout;
    const int base = blockIdx.x * 1024 + threadIdx.x;
    float4 v0 = in[base], v1 = in[base + 256], v2 = in[base + 512],
           v3 = in[base + 768];
    out[base]       = make_uint2(pack2h(v0.x, v0.y), pack2h(v0.z, v0.w));
    out[base + 256] = make_uint2(pack2h(v1.x, v1.y), pack2h(v1.z, v1.w));
    out[base + 512] = make_uint2(pack2h(v2.x, v2.y), pack2h(v2.z, v2.w));
    out[base + 768] = make_uint2(pack2h(v3.x, v3.y), pack2h(v3.z, v3.w));
}

// ---- transpose: W (1024x1024 fp32) -> W^T hi fp16 plane -------------------
__global__ void __launch_bounds__(256) k_tr(const float* __restrict__ W0,
                                            const float* __restrict__ W1,
                                            const float* __restrict__ W2)
{
    __shared__ float tile[64][65];
    const int z = blockIdx.z;
    const float* W = (z == 0) ? W0 : (z == 1) ? W1 : W2;
    const int r0 = blockIdx.y * 64, c0 = blockIdx.x * 64;
    const int row = threadIdx.x >> 2, c4 = (threadIdx.x & 3) * 16;

#pragma unroll
    for (int i = 0; i < 4; ++i) {
        float4 v = *(const float4*)(W + (size_t)(r0 + row) * 1024 + c0 + c4 + i * 4);
        tile[row][c4 + i * 4 + 0] = v.x; tile[row][c4 + i * 4 + 1] = v.y;
        tile[row][c4 + i * 4 + 2] = v.z; tile[row][c4 + i * 4 + 3] = v.w;
    }
    __syncthreads();

    uint32_t hb[8];
#pragma unroll
    for (int i = 0; i < 8; ++i)
        hb[i] = pack2h(tile[c4 + 2 * i][row], tile[c4 + 2 * i + 1][row]);
    const size_t o = (size_t)z * WSZ + (size_t)(c0 + row) * 1024 + r0 + c4;
    *(uint4*)&g_wth[o]     = make_uint4(hb[0], hb[1], hb[2], hb[3]);
    *(uint4*)&g_wth[o + 8] = make_uint4(hb[4], hb[5], hb[6], hb[7]);
}

// ---- fp16 mma.sync GEMM: C = Ah*Bh^T --------------------------------------
// OUT: 0 = fp32 C, 2 = fp16 hi C (scaled by s0 for z==0).
#define RP    80
#define PLANE 10240
#define BUF   20480   /* Ah | Bh */
#define DSM2  61440   /* 3 buffers */

template <int OUT>
__global__ void __launch_bounds__(256, 2) k_gemm(
    const __half* __restrict__ Ah, int lda, int aoff,
    const __half* __restrict__ Bh,
    float* __restrict__ Cf, __half* __restrict__ Ch,
    int ldc, int coff, float s0)
{
    extern __shared__ __align__(16) char sm[];
    const int tid = threadIdx.x;
    const int lane = tid & 31, wid = tid >> 5;
    const int wm = wid & 1, wn = wid >> 1;
    const int z = blockIdx.z;
    const int m0 = blockIdx.y * 128, n0 = blockIdx.x * 128;
    const float cs = (z == 0) ? s0 : 1.f;

    const __half* Azh = Ah + (size_t)z * aoff;
    const __half* Bzh = Bh + (size_t)z * WSZ;

    const int row = tid >> 1, half = tid & 1;
    const __half* pAh = Azh + (size_t)(m0 + row) * lda + half * 16;
    const __half* pBh = Bzh + (size_t)(n0 + row) * 1024 + half * 16;
    const uint32_t sb = smem_u32(sm);
    const uint32_t drow = (uint32_t)row * RP + half * 32;

    auto load_slab = [&](int buf, int kt) {
        const uint32_t d = sb + buf * BUF + drow;
        const int ko = kt * 32;
        cpa16(d,         pAh + ko); cpa16(d + 16,         pAh + ko + 8);
        cpa16(d + PLANE, pBh + ko); cpa16(d + PLANE + 16, pBh + ko + 8);
        asm volatile("cp.async.commit_group;" ::: "memory");
    };

    float acc[4][4][4];
#pragma unroll
    for (int i = 0; i < 4; ++i)
#pragma unroll
        for (int j = 0; j < 4; ++j)
#pragma unroll
            for (int r = 0; r < 4; ++r) acc[i][j][r] = 0.f;

    load_slab(0, 0);
    load_slab(1, 1);

    const uint32_t a_base = (uint32_t)(wm * 64 + (lane & 15)) * RP + (lane >> 4) * 16;
    const uint32_t b_base = PLANE + (uint32_t)(wn * 32 + (lane & 15)) * RP
                            + (lane >> 4) * 16;

    int cur = 0, pre = 2;
    for (int kt = 0; kt < 32; ++kt) {
        if (kt < 31) asm volatile("cp.async.wait_group 1;" ::: "memory");
        else         asm volatile("cp.async.wait_group 0;" ::: "memory");
        __syncthreads();
        if (kt + 2 < 32) load_slab(pre, kt + 2);
        const uint32_t bufb = sb + cur * BUF;
#pragma unroll
        for (int s = 0; s < 2; ++s) {
            const uint32_t stepb = bufb + s * 32;
            uint32_t ah[4][4], bh[2][4];
#pragma unroll
            for (int mi = 0; mi < 4; ++mi) ldsm4(ah[mi], stepb + a_base + mi * 1280);
#pragma unroll
            for (int p = 0; p < 2; ++p) ldsm4(bh[p], stepb + b_base + p * 1280);
#pragma unroll
            for (int mi = 0; mi < 4; ++mi)
#pragma unroll
                for (int p = 0; p < 2; ++p) {
                    mma_f16(acc[mi][2 * p],     ah[mi], bh[p][0], bh[p][2]);
                    mma_f16(acc[mi][2 * p + 1], ah[mi], bh[p][1], bh[p][3]);
                }
        }
        cur = (cur == 2) ? 0 : cur + 1;
        pre = (pre == 2) ? 0 : pre + 1;
    }

    const int t4 = lane >> 2, t2 = lane & 3;
#pragma unroll
    for (int mi = 0; mi < 4; ++mi) {
        const int r0 = m0 + wm * 64 + mi * 16 + t4;
#pragma unroll
        for (int nj = 0; nj < 4; ++nj) {
            const int cc = n0 + wn * 32 + (nj >> 1) * 16 + (nj & 1) * 8 + 2 * t2;
            const float* c = acc[mi][nj];
            const size_t o = (size_t)r0 * ldc + (size_t)z * coff + cc;
            if (OUT == 0) {
                *(float2*)&Cf[o]           = make_float2(c[0], c[1]);
                *(float2*)&Cf[o + 8 * ldc] = make_float2(c[2], c[3]);
            } else {
                *(uint32_t*)&Ch[o]           = pack2h(c[0] * cs, c[1] * cs);
                *(uint32_t*)&Ch[o + 8 * ldc] = pack2h(c[2] * cs, c[3] * cs);
            }
        }
    }
}

// ---- HMMA flash attention: QK 1-term, PV 1-term, exp2-domain softmax ------
#define RPA   144
#define QPL   18432           /* 128*144: Q hi plane */
#define KVSL  36864           /* Kh | Vh */
#define ADSM  92160           /* QPL + 2*KVSL */

__global__ void __launch_bounds__(256) k_att()
{
    extern __shared__ __align__(16) char sm[];
    const int tid = threadIdx.x;
    const int lane = tid & 31, wid = tid >> 5;
    const int n = blockIdx.y >> 4, h = blockIdx.y & 15;
    const int l0 = blockIdx.x * 128;
    const uint32_t sb = smem_u32(sm);

    const int row = tid >> 1, half = tid & 1;
    const size_t qrow = (size_t)(n * LSEQ + l0 + row) * QKVC + h * 64 + half * 32;
    const uint32_t drow = (uint32_t)row * RPA + half * 64;

    {
        const __half* sh = g_qkvh + qrow;
#pragma unroll
        for (int j = 0; j < 4; ++j)
            cpa16(sb + drow + j * 16, sh + j * 8);
    }
    const size_t krow0 = (size_t)(n * LSEQ + row) * QKVC + 1024 + h * 64 + half * 32;
    auto load_kv = [&](int buf, int t) {
        const uint32_t d = sb + QPL + buf * KVSL + drow;
        const size_t src = krow0 + (size_t)t * 128 * QKVC;
#pragma unroll
        for (int j = 0; j < 4; ++j) {
            cpa16(d + j * 16,         g_qkvh + src + j * 8);           // Kh
            cpa16(d + 18432 + j * 16, g_qkvh + src + 1024 + j * 8);    // Vh
        }
        asm volatile("cp.async.commit_group;" ::: "memory");
    };
    load_kv(0, 0);
    load_kv(1, 1);

    float o[8][4];
#pragma unroll
    for (int i = 0; i < 8; ++i)
#pragma unroll
        for (int r = 0; r < 4; ++r) o[i][r] = 0.f;
    float m0 = -3.0e38f, m1 = -3.0e38f, l0s = 0.f, l1s = 0.f;

    const int wr = wid * 16;
    const uint32_t a_addr = (uint32_t)(wr + (lane & 15)) * RPA + (lane >> 4) * 16;
    const uint32_t vrow = (uint32_t)(lane & 15) * RPA + ((lane & 16) ? 16 : 0);

    for (int t = 0; t < 16; ++t) {
        if (t < 14) asm volatile("cp.async.wait_group 1;" ::: "memory");
        else        asm volatile("cp.async.wait_group 0;" ::: "memory");
        __syncthreads();
        const uint32_t KH = sb + QPL + (t & 1) * KVSL;
        const uint32_t VH = KH + 18432;

        float sc[16][4];
#pragma unroll
        for (int f = 0; f < 16; ++f)
#pragma unroll
            for (int r = 0; r < 4; ++r) sc[f][r] = 0.f;

#pragma unroll
        for (int s = 0; s < 4; ++s) {
            uint32_t aqh[4];
            ldsm4(aqh, sb + a_addr + s * 32);
#pragma unroll
            for (int nb = 0; nb < 8; ++nb) {
                const uint32_t kaddr = (uint32_t)(nb * 16 + (lane & 15)) * RPA
                                       + s * 32 + (lane >> 4) * 16;
                uint32_t bh[4];
                ldsm4(bh, KH + kaddr);
                mma_f16(sc[2 * nb],     aqh, bh[0], bh[2]);
                mma_f16(sc[2 * nb + 1], aqh, bh[1], bh[3]);
            }
        }

        float rm0 = -3.0e38f, rm1 = -3.0e38f;
#pragma unroll
        for (int f = 0; f < 16; ++f) {
            rm0 = fmaxf(rm0, fmaxf(sc[f][0], sc[f][1]));
            rm1 = fmaxf(rm1, fmaxf(sc[f][2], sc[f][3]));
        }
#pragma unroll
        for (int off = 1; off <= 2; off <<= 1) {
            rm0 = fmaxf(rm0, __shfl_xor_sync(0xffffffffu, rm0, off));
            rm1 = fmaxf(rm1, __shfl_xor_sync(0xffffffffu, rm1, off));
        }
        const float mn0 = fmaxf(m0, rm0), mn1 = fmaxf(m1, rm1);
        const float al0 = ex2(m0 - mn0), al1 = ex2(m1 - mn1);
        m0 = mn0; m1 = mn1;
        float rs0 = 0.f, rs1 = 0.f;
#pragma unroll
        for (int f = 0; f < 16; ++f) {
            sc[f][0] = ex2(sc[f][0] - mn0); sc[f][1] = ex2(sc[f][1] - mn0);
            sc[f][2] = ex2(sc[f][2] - mn1); sc[f][3] = ex2(sc[f][3] - mn1);
            rs0 += sc[f][0] + sc[f][1];
            rs1 += sc[f][2] + sc[f][3];
        }
#pragma unroll
        for (int off = 1; off <= 2; off <<= 1) {
            rs0 += __shfl_xor_sync(0xffffffffu, rs0, off);
            rs1 += __shfl_xor_sync(0xffffffffu, rs1, off);
        }
        l0s = l0s * al0 + rs0;
        l1s = l1s * al1 + rs1;
#pragma unroll
        for (int i = 0; i < 8; ++i) {
            o[i][0] *= al0; o[i][1] *= al0; o[i][2] *= al1; o[i][3] *= al1;
        }

#pragma unroll
        for (int g = 0; g < 8; ++g) {
            uint32_t ap[4];
            ap[0] = pack2h(sc[2 * g][0],     sc[2 * g][1]);
            ap[1] = pack2h(sc[2 * g][2],     sc[2 * g][3]);
            ap[2] = pack2h(sc[2 * g + 1][0], sc[2 * g + 1][1]);
            ap[3] = pack2h(sc[2 * g + 1][2], sc[2 * g + 1][3]);
#pragma unroll
            for (int nbp = 0; nbp < 4; ++nbp) {
                uint32_t bv[4];
                ldsm4t(bv, VH + vrow + (uint32_t)g * 16 * RPA + nbp * 32);
                mma_f16(o[2 * nbp],     ap, bv[0], bv[1]);
                mma_f16(o[2 * nbp + 1], ap, bv[2], bv[3]);
            }
        }
        __syncthreads();
        if (t + 2 < 16) load_kv(t & 1, t + 2);
    }

    const float inv0 = 1.0f / l0s, inv1 = 1.0f / l1s;
    const int t4 = lane >> 2, t2 = lane & 3;
    const size_t r0 = (size_t)(n * LSEQ + l0 + wr + t4) * EDIM + h * 64 + 2 * t2;
    const size_t r1 = r0 + 8 * EDIM;
#pragma unroll
    for (int nb = 0; nb < 8; ++nb) {
        *(uint32_t*)&g_atth[r0 + 8 * nb] = pack2h(o[nb][0] * inv0, o[nb][1] * inv0);
        *(uint32_t*)&g_atth[r1 + 8 * nb] = pack2h(o[nb][2] * inv1, o[nb][3] * inv1);
    }
}

extern "C" void kernel_launch(void* const* d_in, const int* in_sizes, int n_in,
                              void* d_out, int out_size)
{
    const float* x    = (const float*)d_in[0];
    const float* Wq   = (const float*)d_in[1];
    const float* Wk   = (const float*)d_in[2];
    const float* Wv   = (const float*)d_in[3];
    const float* Wqp  = (const float*)d_in[4];
    const float* Wkp  = (const float*)d_in[5];
    const float* Wvp  = (const float*)d_in[6];
    const float* Wout = (const float*)d_in[7];
    float* outp = (float*)d_out;

    cudaFuncSetAttribute((const void*)k_gemm<0>,
                         cudaFuncAttributeMaxDynamicSharedMemorySize, DSM2);
    cudaFuncSetAttribute((const void*)k_gemm<2>,
                         cudaFuncAttributeMaxDynamicSharedMemorySize, DSM2);
    cudaFuncSetAttribute((const void*)k_att,
                         cudaFuncAttributeMaxDynamicSharedMemorySize, ADSM);

    __half *xh, *wph, *wth, *wch, *wouth, *qkvh, *atth;
    cudaGetSymbolAddress((void**)&xh, g_xh);
    cudaGetSymbolAddress((void**)&wph, g_wph);
    cudaGetSymbolAddress((void**)&wth, g_wth);
    cudaGetSymbolAddress((void**)&wch, g_wch);
    cudaGetSymbolAddress((void**)&wouth, g_wouth);
    cudaGetSymbolAddress((void**)&qkvh, g_qkvh);
    cudaGetSymbolAddress((void**)&atth, g_atth);

    // 0-2: conversions (MLP-4 variants)
    k_cvtx<<<MTOK * EDIM / 4096, 256>>>((const float4*)x, (uint2*)xh);
    k_tr<<<dim3(16, 16, 3), 256>>>(Wq, Wk, Wv);
    k_cvtw<<<dim3(256, 1, 4), 256>>>((const float4*)Wqp, (const float4*)Wkp,
                                     (const float4*)Wvp, (const float4*)Wout,
                                     (uint2*)wph, (uint2*)wouth);

    // 3: combine Wc_z = Wzp @ Wz (1-term; q block pre-scaled by 0.125*log2e)
    k_gemm<2><<<dim3(8, 8, 3), 256, DSM2>>>(wph, 1024, (int)WSZ, wth,
                                            nullptr, wch, 1024, (int)WSZ,
                                            0.125f * 1.4426950408889634f);
    // 4: qkv = x @ Wc^T (fp16 hi out)
    k_gemm<2><<<dim3(8, 64, 3), 256, DSM2>>>(xh, EDIM, 0, wch,
                                             nullptr, qkvh, QKVC, 1024, 1.f);
    // 5: attention  <- ncu capture target
    k_att<<<dim3(LSEQ / 128, NB * NH), 256, ADSM>>>();
    // 6: out = att @ Wout^T (fp32 out)
    k_gemm<0><<<dim3(8, 64, 1), 256, DSM2>>>(atth, EDIM, 0, wouth,
                                             outp, nullptr, EDIM, 0, 1.f);
}